// round 10
// baseline (speedup 1.0000x reference)
#include <cuda_runtime.h>
#include <math.h>

// Problem constants
#define BATCH   2
#define NSEQ    2048
#define HEADS   8
#define DHEAD   64
#define DIMM    512
#define BHDIM   (BATCH*HEADS)        // 16
#define MROWS   (BATCH*NSEQ)         // 4096
#define QROWS   (BHDIM*NSEQ)         // 32768
#define TVALS   1025                 // 2*512+1
#define PLD     1028                 // padded row stride for P
#define RELTLD  1152                 // padded relT cols (9 tiles of 128)
#define SCALE_F 0.125f
#define QT_BH   (DHEAD*NSEQ)         // per-bh stride of [d][n] layout

typedef unsigned long long u64;

// ---------------- device scratch ---------------------------------------------
__device__ float g_Q [QROWS * DHEAD];                 // [bh][n][d] (scaled)
__device__ float g_Qt[BHDIM * DHEAD * NSEQ];          // [bh][d][n] (scaled)
__device__ float g_Kt[BHDIM * DHEAD * NSEQ];          // [bh][d][n]
__device__ float g_V [QROWS * DHEAD];                 // [bh][n][d]
__device__ float g_P [(size_t)QROWS * PLD];           // [bh*n][t] (pre-scaled)
__device__ float g_O [MROWS * DIMM];                  // [b*n][h*d]
__device__ float g_relT[DHEAD * RELTLD];              // [d][t] zero-padded

// ---------------- packed f32x2 primitives ------------------------------------
__device__ __forceinline__ u64 pack2(float lo, float hi) {
    u64 r; asm("mov.b64 %0, {%1, %2};" : "=l"(r) : "f"(lo), "f"(hi)); return r;
}
__device__ __forceinline__ u64 dup2(float v) {
    u64 r; asm("mov.b64 %0, {%1, %1};" : "=l"(r) : "f"(v)); return r;
}
__device__ __forceinline__ void unpack2(u64 v, float& lo, float& hi) {
    asm("mov.b64 {%0, %1}, %2;" : "=f"(lo), "=f"(hi) : "l"(v));
}
__device__ __forceinline__ void fma2(u64& d, u64 a, u64 b) {
    asm("fma.rn.f32x2 %0, %1, %2, %0;" : "+l"(d) : "l"(a), "l"(b));
}
__device__ __forceinline__ void mul2(u64& d, u64 a) {
    asm("mul.rn.f32x2 %0, %0, %1;" : "+l"(d) : "l"(a));
}

// ---------------- cp.async helpers --------------------------------------------
__device__ __forceinline__ void cp16(float* dst, const float* src) {
    unsigned s = (unsigned)__cvta_generic_to_shared(dst);
    asm volatile("cp.async.ca.shared.global [%0], [%1], 16;" :: "r"(s), "l"(src));
}
#define CP_COMMIT() asm volatile("cp.async.commit_group;")
#define CP_WAIT0()  asm volatile("cp.async.wait_group 0;")

// ---------------- micro tiles --------------------------------------------------
__device__ __forceinline__ void fma8x8(float4 a0, float4 a1,
                                       float4 b0, float4 b1, u64 (&c)[8][4]) {
    u64 p0 = pack2(b0.x, b0.y), p1 = pack2(b0.z, b0.w);
    u64 p2 = pack2(b1.x, b1.y), p3 = pack2(b1.z, b1.w);
    float as[8] = {a0.x, a0.y, a0.z, a0.w, a1.x, a1.y, a1.z, a1.w};
    #pragma unroll
    for (int ii = 0; ii < 8; ii++) {
        u64 ad = dup2(as[ii]);
        fma2(c[ii][0], ad, p0); fma2(c[ii][1], ad, p1);
        fma2(c[ii][2], ad, p2); fma2(c[ii][3], ad, p3);
    }
}
// 8 rows x 4 cols (QK in 512-thread flash)
__device__ __forceinline__ void fma8x4(float4 a0, float4 a1, float4 b,
                                       u64 (&c)[8][2]) {
    u64 p0 = pack2(b.x, b.y), p1 = pack2(b.z, b.w);
    float as[8] = {a0.x, a0.y, a0.z, a0.w, a1.x, a1.y, a1.z, a1.w};
    #pragma unroll
    for (int ii = 0; ii < 8; ii++) {
        u64 ad = dup2(as[ii]);
        fma2(c[ii][0], ad, p0); fma2(c[ii][1], ad, p1);
    }
}
// 8 rows x 2 cols (PV in 512-thread flash)
__device__ __forceinline__ void fma8x2(float4 a0, float4 a1, u64 bp, u64 (&c)[8]) {
    float as[8] = {a0.x, a0.y, a0.z, a0.w, a1.x, a1.y, a1.z, a1.w};
    #pragma unroll
    for (int ii = 0; ii < 8; ii++)
        fma2(c[ii], dup2(as[ii]), bp);
}

__device__ __forceinline__ void unpack_acc8(const u64 (&acc)[8][4], float (&s)[8][8]) {
    #pragma unroll
    for (int ii = 0; ii < 8; ii++)
        #pragma unroll
        for (int p = 0; p < 4; p++)
            unpack2(acc[ii][p], s[ii][2*p], s[ii][2*p+1]);
}

// ---------------- 128x128 sgemm core (BK=16, 256 thr, 8x8/thread) ------------
__device__ __forceinline__ void sgemm128(
    const float* __restrict__ A, int lda,
    const float* __restrict__ B, int ldb,
    int kdim, u64 (&acc)[8][4],
    float (*Ats)[128], float (*Bs)[128])
{
    const int tid = threadIdx.x;
    const int ty  = tid >> 4, tx = tid & 15;
    const int ar  = tid >> 1;
    const int ak  = (tid & 1) << 3;
    const int br0 = tid >> 5;
    const int bc  = (tid & 31) << 2;

    float4 a0 = *(const float4*)(A + (size_t)ar * lda + ak);
    float4 a1 = *(const float4*)(A + (size_t)ar * lda + ak + 4);
    float4 b0 = *(const float4*)(B + (size_t)br0 * ldb + bc);
    float4 b1 = *(const float4*)(B + (size_t)(br0 + 8) * ldb + bc);

    for (int k0 = 0; k0 < kdim; k0 += 16) {
        Ats[ak + 0][ar] = a0.x; Ats[ak + 1][ar] = a0.y;
        Ats[ak + 2][ar] = a0.z; Ats[ak + 3][ar] = a0.w;
        Ats[ak + 4][ar] = a1.x; Ats[ak + 5][ar] = a1.y;
        Ats[ak + 6][ar] = a1.z; Ats[ak + 7][ar] = a1.w;
        *(float4*)(&Bs[br0][bc])     = b0;
        *(float4*)(&Bs[br0 + 8][bc]) = b1;
        __syncthreads();
        if (k0 + 16 < kdim) {
            a0 = *(const float4*)(A + (size_t)ar * lda + k0 + 16 + ak);
            a1 = *(const float4*)(A + (size_t)ar * lda + k0 + 16 + ak + 4);
            b0 = *(const float4*)(B + (size_t)(k0 + 16 + br0) * ldb + bc);
            b1 = *(const float4*)(B + (size_t)(k0 + 24 + br0) * ldb + bc);
        }
        #pragma unroll
        for (int kk = 0; kk < 16; kk++) {
            float4 av0 = *(const float4*)(&Ats[kk][ty << 3]);
            float4 av1 = *(const float4*)(&Ats[kk][(ty << 3) + 4]);
            float4 bv0 = *(const float4*)(&Bs[kk][tx << 3]);
            float4 bv1 = *(const float4*)(&Bs[kk][(tx << 3) + 4]);
            fma8x8(av0, av1, bv0, bv1, acc);
        }
        __syncthreads();
    }
}

// ---------------- kernel 0: transpose+pad rel_emb ----------------------------
__global__ void __launch_bounds__(256) transpose_rel_kernel(
    const float* __restrict__ rel, float* __restrict__ relT)
{
    int idx = blockIdx.x * 256 + threadIdx.x;
    if (idx < DHEAD * RELTLD) {
        int d = idx / RELTLD;
        int t = idx % RELTLD;
        relT[idx] = (t < TVALS) ? rel[(size_t)t * DHEAD + d] : 0.0f;
    }
}

// ---------------- kernel 1: fused QKV projection (128x128 tiles) -------------
__global__ void __launch_bounds__(256, 2) gemm_qkv_kernel(
    const float* __restrict__ x,
    const float* __restrict__ Wq, const float* __restrict__ Wkv,
    float* __restrict__ Q, float* __restrict__ Qt,
    float* __restrict__ Kt, float* __restrict__ V)
{
    __shared__ float Ats[16][128];
    __shared__ float Bs[16][128];

    const int m0 = blockIdx.x << 7;
    const int c0 = blockIdx.y << 7;

    const float* W; int wcol, ldw;
    if (c0 < 512) { W = Wq;  wcol = c0;       ldw = 512;  }
    else          { W = Wkv; wcol = c0 - 512; ldw = 1024; }

    u64 acc[8][4] = {};
    sgemm128(x + (size_t)m0 * DIMM, DIMM, W + wcol, ldw, DIMM, acc, Ats, Bs);

    float s[8][8];
    unpack_acc8(acc, s);

    const int ty = threadIdx.x >> 4, tx = threadIdx.x & 15;
    const int colb = c0 + (tx << 3);

    if (c0 < 512) {
        #pragma unroll
        for (int ii = 0; ii < 8; ii++)
            #pragma unroll
            for (int jj = 0; jj < 8; jj++) s[ii][jj] *= SCALE_F;
        #pragma unroll
        for (int ii = 0; ii < 8; ii++) {
            int r = m0 + (ty << 3) + ii;
            int b = r >> 11, n = r & 2047;
            int head = (colb & 511) >> 6, dl = colb & 63;
            size_t base = (((size_t)(b * HEADS + head)) * NSEQ + n) * DHEAD + dl;
            *(float4*)(Q + base)     = make_float4(s[ii][0], s[ii][1], s[ii][2], s[ii][3]);
            *(float4*)(Q + base + 4) = make_float4(s[ii][4], s[ii][5], s[ii][6], s[ii][7]);
        }
        #pragma unroll
        for (int jj = 0; jj < 8; jj++) {
            int col = colb + jj;
            int head = (col & 511) >> 6, dl = col & 63;
            #pragma unroll
            for (int g = 0; g < 2; g++) {
                int r = m0 + (ty << 3) + g * 4;
                int b = r >> 11, n = r & 2047;
                size_t base = (size_t)(b * HEADS + head) * QT_BH + (size_t)dl * NSEQ + n;
                *(float4*)(Qt + base) = make_float4(s[g*4+0][jj], s[g*4+1][jj],
                                                    s[g*4+2][jj], s[g*4+3][jj]);
            }
        }
    } else if (c0 < 1024) {
        #pragma unroll
        for (int jj = 0; jj < 8; jj++) {
            int col = colb + jj;
            int head = (col & 511) >> 6, dl = col & 63;
            #pragma unroll
            for (int g = 0; g < 2; g++) {
                int r = m0 + (ty << 3) + g * 4;
                int b = r >> 11, n = r & 2047;
                size_t base = (size_t)(b * HEADS + head) * QT_BH + (size_t)dl * NSEQ + n;
                *(float4*)(Kt + base) = make_float4(s[g*4+0][jj], s[g*4+1][jj],
                                                    s[g*4+2][jj], s[g*4+3][jj]);
            }
        }
    } else {
        #pragma unroll
        for (int ii = 0; ii < 8; ii++) {
            int r = m0 + (ty << 3) + ii;
            int b = r >> 11, n = r & 2047;
            int head = (colb & 511) >> 6, dl = colb & 63;
            size_t base = (((size_t)(b * HEADS + head)) * NSEQ + n) * DHEAD + dl;
            *(float4*)(V + base)     = make_float4(s[ii][0], s[ii][1], s[ii][2], s[ii][3]);
            *(float4*)(V + base + 4) = make_float4(s[ii][4], s[ii][5], s[ii][6], s[ii][7]);
        }
    }
}

// ---------------- kernel 2: P = Qscaled @ relT  (32768 x 1025 x 64) ----------
__global__ void __launch_bounds__(256, 2) gemm_p_kernel(
    const float* __restrict__ Q, const float* __restrict__ relT,
    float* __restrict__ P)
{
    __shared__ float Ats[16][128];
    __shared__ float Bs[16][128];

    const int m0 = blockIdx.x << 7;
    const int t0 = blockIdx.y << 7;

    u64 acc[8][4] = {};
    sgemm128(Q + (size_t)m0 * DHEAD, DHEAD, relT + t0, RELTLD, DHEAD, acc, Ats, Bs);

    float s[8][8];
    unpack_acc8(acc, s);

    const int ty = threadIdx.x >> 4, tx = threadIdx.x & 15;
    const int colb = t0 + (tx << 3);
    const bool full = (t0 + 127) < TVALS;

    #pragma unroll
    for (int ii = 0; ii < 8; ii++) {
        size_t base = (size_t)(m0 + (ty << 3) + ii) * PLD + colb;
        if (full) {
            *(float4*)(P + base)     = make_float4(s[ii][0], s[ii][1], s[ii][2], s[ii][3]);
            *(float4*)(P + base + 4) = make_float4(s[ii][4], s[ii][5], s[ii][6], s[ii][7]);
        } else {
            #pragma unroll
            for (int jj = 0; jj < 8; jj++)
                if (colb + jj < TVALS) P[base + jj] = s[ii][jj];
        }
    }
}

// ---------------- kernel 3: flash attention, Br=Bc=128, 512 threads ----------
// grid (16, 16), 512 threads (16 warps), 224 KB dyn smem, 1 CTA/SM.
// Per-thread: QK 8x4 (s2[8][2]), PV 8x2 (o2[8]); regs capped at 128.
__global__ void __launch_bounds__(512, 1) flash_kernel(
    const float* __restrict__ Qt, const float* __restrict__ Kt,
    const float* __restrict__ V, const float* __restrict__ P,
    float* __restrict__ O)
{
    extern __shared__ float smf[];
    float* Qts  = smf;                   // [64][128]
    float* Ktb0 = smf + 8192;            // [64][128] double-buffered
    float* Ktb1 = smf + 16384;
    float* Vb0  = smf + 24576;           // [128][64] double-buffered
    float* Vb1  = smf + 32768;
    float* Pts  = smf + 40960;           // [128][128] swizzled

    const int bh = blockIdx.y;
    const int n0 = blockIdx.x << 7;
    const float* Qb = Qt + (size_t)bh * QT_BH;
    const float* Kb = Kt + (size_t)bh * QT_BH;
    const float* Vg = V  + (size_t)bh * NSEQ * DHEAD;
    const float* Pb = P  + (size_t)bh * NSEQ * PLD;

    const int tid = threadIdx.x;
    const int ty  = tid >> 5;            // 0..15 -> rows ty*8..+7
    const int tx  = tid & 31;            // 0..31 -> QK cols tx*4..+3, PV cols tx*2..+1

    // staging coords: K/Q tiles are 2048 float4 -> 4 per thread
    // stage Q (plain stores; visible after first barrier)
    #pragma unroll
    for (int q = 0; q < 4; q++) {
        int idx = (q << 9) + tid;
        int d = idx >> 5, c = (idx & 31) << 2;
        *(float4*)(Qts + d * 128 + c) =
            *(const float4*)(Qb + (size_t)d * NSEQ + n0 + c);
    }

    // prologue: cp.async tile 0
    #pragma unroll
    for (int q = 0; q < 4; q++) {
        int idx = (q << 9) + tid;
        int d = idx >> 5, c = (idx & 31) << 2;
        cp16(Ktb0 + d * 128 + c, Kb + (size_t)d * NSEQ + c);
    }
    #pragma unroll
    for (int q = 0; q < 4; q++) {
        int idx = (q << 9) + tid;
        int row = idx >> 4, c = (idx & 15) << 2;
        cp16(Vb0 + row * 64 + c, Vg + (size_t)row * DHEAD + c);
    }
    CP_COMMIT();

    float m_i[8], l_i[8];
    u64 o2[8];
    #pragma unroll
    for (int ii = 0; ii < 8; ii++) {
        m_i[ii] = -1e30f; l_i[ii] = 0.0f; o2[ii] = 0ull;
    }

    int cur = 0;
    for (int jt = 0; jt < NSEQ / 128; jt++) {
        const int j0 = jt << 7;
        const float* Kc = cur ? Ktb1 : Ktb0;
        const float* Vc = cur ? Vb1  : Vb0;

        CP_WAIT0();
        __syncthreads();                                   // A

        // ---- S = Q K^T (8x4 per thread) --------------------------------------
        u64 s2[8][2] = {};
        #pragma unroll 4
        for (int d = 0; d < 64; d++) {
            float4 av0 = *(const float4*)(Qts + d * 128 + (ty << 3));
            float4 av1 = *(const float4*)(Qts + d * 128 + (ty << 3) + 4);
            float4 bv  = *(const float4*)(Kc  + d * 128 + (tx << 2));
            fma8x4(av0, av1, bv, s2);
        }

        // ---- bias + online softmax -------------------------------------------
        float s[8][4];
        float rowmax[8];
        #pragma unroll
        for (int ii = 0; ii < 8; ii++) {
            unpack2(s2[ii][0], s[ii][0], s[ii][1]);
            unpack2(s2[ii][1], s[ii][2], s[ii][3]);
            int n = n0 + (ty << 3) + ii;
            const float* prow = Pb + (size_t)n * PLD;
            int basei = n - j0 + 512 - (tx << 2);
            rowmax[ii] = -1e30f;
            #pragma unroll
            for (int jj = 0; jj < 4; jj++) {
                int idx = basei - jj;
                idx = idx < 0 ? 0 : (idx > 1024 ? 1024 : idx);
                float v = s[ii][jj] + prow[idx];
                s[ii][jj] = v;
                rowmax[ii] = fmaxf(rowmax[ii], v);
            }
        }
        #pragma unroll
        for (int msk = 1; msk < 32; msk <<= 1)
            #pragma unroll
            for (int ii = 0; ii < 8; ii++)
                rowmax[ii] = fmaxf(rowmax[ii],
                                   __shfl_xor_sync(0xffffffffu, rowmax[ii], msk));

        float rs[8];
        #pragma unroll
        for (int ii = 0; ii < 8; ii++) {
            float mnew = fmaxf(m_i[ii], rowmax[ii]);
            float corr = __expf(m_i[ii] - mnew);
            m_i[ii] = mnew;
            rs[ii] = 0.0f;
            #pragma unroll
            for (int jj = 0; jj < 4; jj++) {
                float p = __expf(s[ii][jj] - mnew);
                s[ii][jj] = p;
                rs[ii] += p;
            }
            l_i[ii] *= corr;
            mul2(o2[ii], dup2(corr));
        }
        #pragma unroll
        for (int msk = 1; msk < 32; msk <<= 1)
            #pragma unroll
            for (int ii = 0; ii < 8; ii++)
                rs[ii] += __shfl_xor_sync(0xffffffffu, rs[ii], msk);
        #pragma unroll
        for (int ii = 0; ii < 8; ii++) l_i[ii] += rs[ii];

        // ---- stage S transposed into Pts (swizzled i-quads) -------------------
        // write: j = tx*4+jj; i-quad q stored at (q ^ ((j>>2)&7)) * 4
        {
            int sw = tx & 7;  // == (j>>2)&7 for j = tx*4+jj, jj<4
            #pragma unroll
            for (int jj = 0; jj < 4; jj++) {
                int j = (tx << 2) + jj;
                *(float4*)(Pts + j * 128 + ((((ty << 1))     ^ sw) << 2)) =
                    make_float4(s[0][jj], s[1][jj], s[2][jj], s[3][jj]);
                *(float4*)(Pts + j * 128 + ((((ty << 1) | 1) ^ sw) << 2)) =
                    make_float4(s[4][jj], s[5][jj], s[6][jj], s[7][jj]);
            }
        }
        __syncthreads();                                   // B

        // ---- issue cp.async for next tile (overlaps PV) -----------------------
        if (jt + 1 < NSEQ / 128) {
            float* Kn = cur ? Ktb0 : Ktb1;
            float* Vn = cur ? Vb0  : Vb1;
            const int jn = j0 + 128;
            #pragma unroll
            for (int q = 0; q < 4; q++) {
                int idx = (q << 9) + tid;
                int d = idx >> 5, c = (idx & 31) << 2;
                cp16(Kn + d * 128 + c, Kb + (size_t)d * NSEQ + jn + c);
            }
            #pragma unroll
            for (int q = 0; q < 4; q++) {
                int idx = (q << 9) + tid;
                int row = idx >> 4, c = (idx & 15) << 2;
                cp16(Vn + row * 64 + c, Vg + (size_t)(jn + row) * DHEAD + c);
            }
            CP_COMMIT();
        }

        // ---- O += P V (8x2 per thread) ----------------------------------------
        #pragma unroll 4
        for (int j = 0; j < 128; j++) {
            int sw = (j >> 2) & 7;
            float4 a0 = *(const float4*)(Pts + j * 128 + ((((ty << 1))     ^ sw) << 2));
            float4 a1 = *(const float4*)(Pts + j * 128 + ((((ty << 1) | 1) ^ sw) << 2));
            float2 bv = *(const float2*)(Vc + j * 64 + (tx << 1));
            fma8x2(a0, a1, pack2(bv.x, bv.y), o2);
        }
        cur ^= 1;
    }

    // epilogue: normalize, write [b][n][h*64+dd]
    const int b = bh >> 3, head = bh & 7;
    #pragma unroll
    for (int ii = 0; ii < 8; ii++) {
        int n = n0 + (ty << 3) + ii;
        float inv = 1.0f / l_i[ii];
        float2 v;
        unpack2(o2[ii], v.x, v.y);
        v.x *= inv; v.y *= inv;
        size_t base = ((size_t)(b * NSEQ + n)) * DIMM + (head << 6) + (tx << 1);
        *(float2*)(O + base) = v;
    }
}

// ---------------- kernel 4: output projection + bias (128x128) ----------------
__global__ void __launch_bounds__(256, 2) gemm_out_kernel(
    const float* __restrict__ O, const float* __restrict__ Wo,
    const float* __restrict__ bo, float* __restrict__ out)
{
    __shared__ float Ats[16][128];
    __shared__ float Bs[16][128];

    const int m0 = blockIdx.x << 7;
    const int n0 = blockIdx.y << 7;

    u64 acc[8][4] = {};
    sgemm128(O + (size_t)m0 * DIMM, DIMM, Wo + n0, DIMM, DIMM, acc, Ats, Bs);

    float s[8][8];
    unpack_acc8(acc, s);

    const int ty = threadIdx.x >> 4, tx = threadIdx.x & 15;
    const int col = n0 + (tx << 3);
    float4 bias0 = *(const float4*)(bo + col);
    float4 bias1 = *(const float4*)(bo + col + 4);
    #pragma unroll
    for (int ii = 0; ii < 8; ii++) {
        size_t base = (size_t)(m0 + (ty << 3) + ii) * DIMM + col;
        *(float4*)(out + base)     = make_float4(s[ii][0] + bias0.x, s[ii][1] + bias0.y,
                                                 s[ii][2] + bias0.z, s[ii][3] + bias0.w);
        *(float4*)(out + base + 4) = make_float4(s[ii][4] + bias1.x, s[ii][5] + bias1.y,
                                                 s[ii][6] + bias1.z, s[ii][7] + bias1.w);
    }
}

// ---------------- launch -------------------------------------------------------
extern "C" void kernel_launch(void* const* d_in, const int* in_sizes, int n_in,
                              void* d_out, int out_size)
{
    const float* x    = (const float*)d_in[0];
    const float* Wq   = (const float*)d_in[1];
    const float* Wkv  = (const float*)d_in[2];
    const float* Wo   = (const float*)d_in[3];
    const float* bo   = (const float*)d_in[4];
    const float* rel  = (const float*)d_in[5];
    float* out = (float*)d_out;

    float *Qp, *Qtp, *Ktp, *Vp, *Pp, *Op, *rTp;
    cudaGetSymbolAddress((void**)&Qp,  g_Q);
    cudaGetSymbolAddress((void**)&Qtp, g_Qt);
    cudaGetSymbolAddress((void**)&Ktp, g_Kt);
    cudaGetSymbolAddress((void**)&Vp,  g_V);
    cudaGetSymbolAddress((void**)&Pp,  g_P);
    cudaGetSymbolAddress((void**)&Op,  g_O);
    cudaGetSymbolAddress((void**)&rTp, g_relT);

    cudaFuncSetAttribute(flash_kernel,
                         cudaFuncAttributeMaxDynamicSharedMemorySize, 229376);

    transpose_rel_kernel<<<(DHEAD * RELTLD + 255) / 256, 256>>>(rel, rTp);
    gemm_qkv_kernel<<<dim3(MROWS / 128, 12), 256>>>(x, Wq, Wkv, Qp, Qtp, Ktp, Vp);
    gemm_p_kernel<<<dim3(QROWS / 128, 9), 256>>>(Qp, rTp, Pp);
    flash_kernel<<<dim3(NSEQ / 128, BHDIM), 512, 229376>>>(Qtp, Ktp, Vp, Pp, Op);
    gemm_out_kernel<<<dim3(MROWS / 128, DIMM / 128), 256>>>(Op, Wo, bo, out);
}

// round 12
// speedup vs baseline: 1.4986x; 1.4986x over previous
#include <cuda_runtime.h>
#include <cuda_bf16.h>
#include <math.h>

#define BATCH   2
#define NSEQ    2048
#define HEADS   8
#define DHEAD   64
#define DIMM    512
#define BHDIM   16
#define MROWS   4096
#define QROWS   32768
#define TVALS   1025
#define PLD     1028
#define RELTLD  1152
#define SCALE_F 0.125f

typedef unsigned long long u64;
typedef unsigned int u32;

// ---------------- device scratch ---------------------------------------------
__device__ float g_Q [QROWS * DHEAD];                 // [bh][n][d] fp32 scaled (for gemm_p)
__device__ __nv_bfloat16 g_Qhi[QROWS * DHEAD];        // [bh][n][d] scaled
__device__ __nv_bfloat16 g_Qlo[QROWS * DHEAD];
__device__ __nv_bfloat16 g_Khi[QROWS * DHEAD];        // [bh][n][d]
__device__ __nv_bfloat16 g_Klo[QROWS * DHEAD];
__device__ __nv_bfloat16 g_Vhi[QROWS * DHEAD];        // [bh][d][n]
__device__ __nv_bfloat16 g_Vlo[QROWS * DHEAD];
__device__ float g_P [(size_t)QROWS * PLD];
__device__ float g_O [MROWS * DIMM];
__device__ float g_relT[DHEAD * RELTLD];

// ---------------- f32x2 (SIMT GEMMs) -------------------------------------------
__device__ __forceinline__ u64 pack2(float lo, float hi) {
    u64 r; asm("mov.b64 %0, {%1, %2};" : "=l"(r) : "f"(lo), "f"(hi)); return r;
}
__device__ __forceinline__ u64 dup2(float v) {
    u64 r; asm("mov.b64 %0, {%1, %1};" : "=l"(r) : "f"(v)); return r;
}
__device__ __forceinline__ void unpack2(u64 v, float& lo, float& hi) {
    asm("mov.b64 {%0, %1}, %2;" : "=f"(lo), "=f"(hi) : "l"(v));
}
__device__ __forceinline__ void fma2(u64& d, u64 a, u64 b) {
    asm("fma.rn.f32x2 %0, %1, %2, %0;" : "+l"(d) : "l"(a), "l"(b));
}
__device__ __forceinline__ void fma8x8(float4 a0, float4 a1,
                                       float4 b0, float4 b1, u64 (&c)[8][4]) {
    u64 p0 = pack2(b0.x, b0.y), p1 = pack2(b0.z, b0.w);
    u64 p2 = pack2(b1.x, b1.y), p3 = pack2(b1.z, b1.w);
    float as[8] = {a0.x, a0.y, a0.z, a0.w, a1.x, a1.y, a1.z, a1.w};
    #pragma unroll
    for (int ii = 0; ii < 8; ii++) {
        u64 ad = dup2(as[ii]);
        fma2(c[ii][0], ad, p0); fma2(c[ii][1], ad, p1);
        fma2(c[ii][2], ad, p2); fma2(c[ii][3], ad, p3);
    }
}
__device__ __forceinline__ void unpack_acc8(const u64 (&a)[8][4], float (&s)[8][8]) {
    #pragma unroll
    for (int ii = 0; ii < 8; ii++)
        #pragma unroll
        for (int p = 0; p < 4; p++)
            unpack2(a[ii][p], s[ii][2*p], s[ii][2*p+1]);
}

// ---------------- bf16 split/pack ----------------------------------------------
__device__ __forceinline__ void bfsplit2(float f0, float f1, u32& hi, u32& lo) {
    __nv_bfloat16 h0 = __float2bfloat16(f0), h1 = __float2bfloat16(f1);
    __nv_bfloat16 g0 = __float2bfloat16(f0 - __bfloat162float(h0));
    __nv_bfloat16 g1 = __float2bfloat16(f1 - __bfloat162float(h1));
    hi = (u32)__bfloat16_as_ushort(h0) | ((u32)__bfloat16_as_ushort(h1) << 16);
    lo = (u32)__bfloat16_as_ushort(g0) | ((u32)__bfloat16_as_ushort(g1) << 16);
}

// ---------------- cp.async ------------------------------------------------------
__device__ __forceinline__ void cp16s(u32 dst, const void* src) {
    asm volatile("cp.async.ca.shared.global [%0], [%1], 16;" :: "r"(dst), "l"(src));
}
#define CP_COMMIT() asm volatile("cp.async.commit_group;")
#define CP_WAIT0()  asm volatile("cp.async.wait_group 0;")

__device__ __forceinline__ u32 smem_u32(const void* p) {
    u32 a;
    asm("{ .reg .u64 t; cvta.to.shared.u64 t, %1; cvt.u32.u64 %0, t; }" : "=r"(a) : "l"(p));
    return a;
}

// ---------------- HMMA: mma.sync m16n8k16 bf16 ----------------------------------
__device__ __forceinline__ void mma_bf16(float* d, const u32* a, const u32* b) {
    asm volatile(
        "mma.sync.aligned.m16n8k16.row.col.f32.bf16.bf16.f32 "
        "{%0,%1,%2,%3}, {%4,%5,%6,%7}, {%8,%9}, {%0,%1,%2,%3};"
        : "+f"(d[0]), "+f"(d[1]), "+f"(d[2]), "+f"(d[3])
        : "r"(a[0]), "r"(a[1]), "r"(a[2]), "r"(a[3]), "r"(b[0]), "r"(b[1]));
}

// ---------------- 128x128 sgemm core (SIMT fp32, proven) -------------------------
__device__ __forceinline__ void sgemm128(
    const float* __restrict__ A, int lda,
    const float* __restrict__ B, int ldb,
    int kdim, u64 (&acc)[8][4], float (*Ats)[128], float (*Bs)[128])
{
    const int tid = threadIdx.x;
    const int ty = tid >> 4, tx = tid & 15;
    const int ar = tid >> 1, ak = (tid & 1) << 3;
    const int br0 = tid >> 5, bc = (tid & 31) << 2;

    float4 a0 = *(const float4*)(A + (size_t)ar * lda + ak);
    float4 a1 = *(const float4*)(A + (size_t)ar * lda + ak + 4);
    float4 b0 = *(const float4*)(B + (size_t)br0 * ldb + bc);
    float4 b1 = *(const float4*)(B + (size_t)(br0 + 8) * ldb + bc);

    for (int k0 = 0; k0 < kdim; k0 += 16) {
        Ats[ak+0][ar]=a0.x; Ats[ak+1][ar]=a0.y; Ats[ak+2][ar]=a0.z; Ats[ak+3][ar]=a0.w;
        Ats[ak+4][ar]=a1.x; Ats[ak+5][ar]=a1.y; Ats[ak+6][ar]=a1.z; Ats[ak+7][ar]=a1.w;
        *(float4*)(&Bs[br0][bc]) = b0;
        *(float4*)(&Bs[br0+8][bc]) = b1;
        __syncthreads();
        if (k0 + 16 < kdim) {
            a0 = *(const float4*)(A + (size_t)ar * lda + k0 + 16 + ak);
            a1 = *(const float4*)(A + (size_t)ar * lda + k0 + 16 + ak + 4);
            b0 = *(const float4*)(B + (size_t)(k0 + 16 + br0) * ldb + bc);
            b1 = *(const float4*)(B + (size_t)(k0 + 24 + br0) * ldb + bc);
        }
        #pragma unroll
        for (int kk = 0; kk < 16; kk++) {
            float4 av0 = *(const float4*)(&Ats[kk][ty << 3]);
            float4 av1 = *(const float4*)(&Ats[kk][(ty << 3) + 4]);
            float4 bv0 = *(const float4*)(&Bs[kk][tx << 3]);
            float4 bv1 = *(const float4*)(&Bs[kk][(tx << 3) + 4]);
            fma8x8(av0, av1, bv0, bv1, acc);
        }
        __syncthreads();
    }
}

// ---------------- kernel 0 --------------------------------------------------------
__global__ void __launch_bounds__(256) transpose_rel_kernel(
    const float* __restrict__ rel, float* __restrict__ relT)
{
    int idx = blockIdx.x * 256 + threadIdx.x;
    if (idx < DHEAD * RELTLD) {
        int d = idx / RELTLD, t = idx % RELTLD;
        relT[idx] = (t < TVALS) ? rel[(size_t)t * DHEAD + d] : 0.0f;
    }
}

// ---------------- kernel 1: QKV projection ----------------------------------------
__global__ void __launch_bounds__(256, 2) gemm_qkv_kernel(
    const float* __restrict__ x,
    const float* __restrict__ Wq, const float* __restrict__ Wkv,
    float* __restrict__ Q,
    __nv_bfloat16* __restrict__ Qhi, __nv_bfloat16* __restrict__ Qlo,
    __nv_bfloat16* __restrict__ Khi, __nv_bfloat16* __restrict__ Klo,
    __nv_bfloat16* __restrict__ Vhi, __nv_bfloat16* __restrict__ Vlo)
{
    __shared__ float Ats[16][128];
    __shared__ float Bs[16][128];
    const int m0 = blockIdx.x << 7;
    const int c0 = blockIdx.y << 7;

    const float* W; int wcol, ldw;
    if (c0 < 512) { W = Wq;  wcol = c0;       ldw = 512;  }
    else          { W = Wkv; wcol = c0 - 512; ldw = 1024; }

    u64 acc[8][4] = {};
    sgemm128(x + (size_t)m0 * DIMM, DIMM, W + wcol, ldw, DIMM, acc, Ats, Bs);
    float s[8][8];
    unpack_acc8(acc, s);

    const int ty = threadIdx.x >> 4, tx = threadIdx.x & 15;
    const int colb = c0 + (tx << 3);
    const int b = m0 >> 11;
    const int nb = (m0 & 2047) + (ty << 3);

    if (c0 < 512) {                       // Q: scale, fp32 + bf16 hi/lo [bh][n][d]
        int head = (colb & 511) >> 6, dl = colb & 63;
        #pragma unroll
        for (int ii = 0; ii < 8; ii++) {
            #pragma unroll
            for (int jj = 0; jj < 8; jj++) s[ii][jj] *= SCALE_F;
            size_t base = (((size_t)(b * HEADS + head)) * NSEQ + nb + ii) * DHEAD + dl;
            *(float4*)(Q + base)     = make_float4(s[ii][0], s[ii][1], s[ii][2], s[ii][3]);
            *(float4*)(Q + base + 4) = make_float4(s[ii][4], s[ii][5], s[ii][6], s[ii][7]);
            uint4 ph, pl;
            bfsplit2(s[ii][0], s[ii][1], ph.x, pl.x);
            bfsplit2(s[ii][2], s[ii][3], ph.y, pl.y);
            bfsplit2(s[ii][4], s[ii][5], ph.z, pl.z);
            bfsplit2(s[ii][6], s[ii][7], ph.w, pl.w);
            *(uint4*)(Qhi + base) = ph;
            *(uint4*)(Qlo + base) = pl;
        }
    } else if (c0 < 1024) {               // K: bf16 hi/lo [bh][n][d]
        int head = (colb & 511) >> 6, dl = colb & 63;
        #pragma unroll
        for (int ii = 0; ii < 8; ii++) {
            uint4 ph, pl;
            bfsplit2(s[ii][0], s[ii][1], ph.x, pl.x);
            bfsplit2(s[ii][2], s[ii][3], ph.y, pl.y);
            bfsplit2(s[ii][4], s[ii][5], ph.z, pl.z);
            bfsplit2(s[ii][6], s[ii][7], ph.w, pl.w);
            size_t base = (((size_t)(b * HEADS + head)) * NSEQ + nb + ii) * DHEAD + dl;
            *(uint4*)(Khi + base) = ph;
            *(uint4*)(Klo + base) = pl;
        }
    } else {                               // V: bf16 hi/lo transposed [bh][d][n]
        #pragma unroll
        for (int jj = 0; jj < 8; jj++) {
            int col = colb + jj;
            int head = (col & 511) >> 6, d = col & 63;
            uint4 ph, pl;
            bfsplit2(s[0][jj], s[1][jj], ph.x, pl.x);
            bfsplit2(s[2][jj], s[3][jj], ph.y, pl.y);
            bfsplit2(s[4][jj], s[5][jj], ph.z, pl.z);
            bfsplit2(s[6][jj], s[7][jj], ph.w, pl.w);
            size_t base = (((size_t)(b * HEADS + head)) * DHEAD + d) * NSEQ + nb;
            *(uint4*)(Vhi + base) = ph;
            *(uint4*)(Vlo + base) = pl;
        }
    }
}

// ---------------- kernel 2: P = Qscaled @ relT ------------------------------------
__global__ void __launch_bounds__(256, 2) gemm_p_kernel(
    const float* __restrict__ Q, const float* __restrict__ relT,
    float* __restrict__ P)
{
    __shared__ float Ats[16][128];
    __shared__ float Bs[16][128];
    const int m0 = blockIdx.x << 7;
    const int t0 = blockIdx.y << 7;

    u64 acc[8][4] = {};
    sgemm128(Q + (size_t)m0 * DHEAD, DHEAD, relT + t0, RELTLD, DHEAD, acc, Ats, Bs);
    float s[8][8];
    unpack_acc8(acc, s);

    const int ty = threadIdx.x >> 4, tx = threadIdx.x & 15;
    const int colb = t0 + (tx << 3);
    const bool full = (t0 + 127) < TVALS;

    #pragma unroll
    for (int ii = 0; ii < 8; ii++) {
        size_t base = (size_t)(m0 + (ty << 3) + ii) * PLD + colb;
        if (full) {
            *(float4*)(P + base)     = make_float4(s[ii][0], s[ii][1], s[ii][2], s[ii][3]);
            *(float4*)(P + base + 4) = make_float4(s[ii][4], s[ii][5], s[ii][6], s[ii][7]);
        } else {
            #pragma unroll
            for (int jj = 0; jj < 8; jj++)
                if (colb + jj < TVALS) P[base + jj] = s[ii][jj];
        }
    }
}

// ---------------- flash smem layout (bytes) ----------------------------------------
// Q/K tiles: 128 rows x 72 bf16 (144B rows); V tiles: 64 rows x 136 bf16 (272B rows)
#define FQH  0
#define FQL  18432
#define FKH0 36864
#define FKL0 55296
#define FKH1 73728
#define FKL1 92160
#define FVH0 110592
#define FVL0 128000
#define FVH1 145408
#define FVL1 162816
#define FSM_TOTAL 180224

__device__ __forceinline__ void stage_kv_tile(
    u32 smb, int buf, int j0, int tid,
    const __nv_bfloat16* Kh, const __nv_bfloat16* Kl,
    const __nv_bfloat16* Vh, const __nv_bfloat16* Vl)
{
    u32 kh = smb + (buf ? FKH1 : FKH0);
    u32 kl = smb + (buf ? FKL1 : FKL0);
    u32 vh = smb + (buf ? FVH1 : FVH0);
    u32 vl = smb + (buf ? FVL1 : FVL0);
    #pragma unroll
    for (int q = 0; q < 4; q++) {                 // K: 128 rows x 8 16B-chunks
        int idx = (q << 8) + tid;
        int r = idx >> 3, ch = idx & 7;
        u32 off = (u32)(r * 144 + ch * 16);
        size_t src = (size_t)(j0 + r) * DHEAD + ch * 8;
        cp16s(kh + off, Kh + src);
        cp16s(kl + off, Kl + src);
    }
    #pragma unroll
    for (int q = 0; q < 4; q++) {                 // V: 64 rows x 16 16B-chunks
        int idx = (q << 8) + tid;
        int d = idx >> 4, ch = idx & 15;
        u32 off = (u32)(d * 272 + ch * 16);
        size_t src = (size_t)d * NSEQ + j0 + ch * 8;
        cp16s(vh + off, Vh + src);
        cp16s(vl + off, Vl + src);
    }
}

// ---------------- kernel 3: HMMA flash attention ------------------------------------
// grid (16,16), 256 threads (8 warps), 176KB dyn smem. Warp w owns rows 16w..16w+15.
__global__ void __launch_bounds__(256, 1) flash_kernel(
    const __nv_bfloat16* __restrict__ Qhi, const __nv_bfloat16* __restrict__ Qlo,
    const __nv_bfloat16* __restrict__ Khi, const __nv_bfloat16* __restrict__ Klo,
    const __nv_bfloat16* __restrict__ Vhi, const __nv_bfloat16* __restrict__ Vlo,
    const float* __restrict__ P, float* __restrict__ O)
{
    extern __shared__ char smc[];
    const u32 smb = smem_u32(smc);
    const __nv_bfloat16* QhS = (const __nv_bfloat16*)(smc + FQH);
    const __nv_bfloat16* QlS = (const __nv_bfloat16*)(smc + FQL);

    const int tid  = threadIdx.x;
    const int wid  = tid >> 5, lane = tid & 31;
    const int ln4  = lane >> 2;                    // 0..7
    const int lm4  = lane & 3;                     // 0..3
    const int bh   = blockIdx.y, n0 = blockIdx.x << 7;
    const int b    = bh >> 3, head = bh & 7;

    const __nv_bfloat16* Qhg = Qhi + ((size_t)bh * NSEQ + n0) * DHEAD;
    const __nv_bfloat16* Qlg = Qlo + ((size_t)bh * NSEQ + n0) * DHEAD;
    const __nv_bfloat16* Khg = Khi + (size_t)bh * NSEQ * DHEAD;
    const __nv_bfloat16* Klg = Klo + (size_t)bh * NSEQ * DHEAD;
    const __nv_bfloat16* Vhg = Vhi + (size_t)bh * DHEAD * NSEQ;
    const __nv_bfloat16* Vlg = Vlo + (size_t)bh * DHEAD * NSEQ;

    // stage Q (once) and K/V tile 0
    #pragma unroll
    for (int q = 0; q < 4; q++) {
        int idx = (q << 8) + tid;
        int r = idx >> 3, ch = idx & 7;
        u32 off = (u32)(r * 144 + ch * 16);
        size_t src = (size_t)r * DHEAD + ch * 8;
        cp16s(smb + FQH + off, Qhg + src);
        cp16s(smb + FQL + off, Qlg + src);
    }
    stage_kv_tile(smb, 0, 0, tid, Khg, Klg, Vhg, Vlg);
    CP_COMMIT();

    // S row indices this thread touches
    const int r0 = (wid << 4) + ln4;               // local rows r0, r0+8
    const float* prow0 = P + ((size_t)bh * NSEQ + n0 + r0) * PLD;
    const float* prow1 = prow0 + 8 * PLD;

    float o[8][4];
    #pragma unroll
    for (int n = 0; n < 8; n++)
        #pragma unroll
        for (int p = 0; p < 4; p++) o[n][p] = 0.0f;
    float lsum0 = 0.0f, lsum1 = 0.0f;

    for (int jt = 0; jt < 16; jt++) {
        const int j0 = jt << 7;
        const int buf = jt & 1;
        const __nv_bfloat16* KhS = (const __nv_bfloat16*)(smc + (buf ? FKH1 : FKH0));
        const __nv_bfloat16* KlS = (const __nv_bfloat16*)(smc + (buf ? FKL1 : FKL0));
        const __nv_bfloat16* VhS = (const __nv_bfloat16*)(smc + (buf ? FVH1 : FVH0));
        const __nv_bfloat16* VlS = (const __nv_bfloat16*)(smc + (buf ? FVL1 : FVL0));

        CP_WAIT0();
        __syncthreads();

        if (jt + 1 < 16)                          // prefetch next tile (overlaps MMA)
            stage_kv_tile(smb, buf ^ 1, j0 + 128, tid, Khg, Klg, Vhg, Vlg);
        CP_COMMIT();

        // ---- S = Q K^T : 16 rows x 128 cols per warp, 3-term split ----------
        float c[16][4];
        #pragma unroll
        for (int n = 0; n < 16; n++)
            #pragma unroll
            for (int p = 0; p < 4; p++) c[n][p] = 0.0f;

        #pragma unroll
        for (int k = 0; k < 4; k++) {
            const int aoff = r0 * 72 + k * 16 + (lm4 << 1);
            u32 qh[4], ql[4];
            qh[0] = *(const u32*)(QhS + aoff);
            qh[1] = *(const u32*)(QhS + aoff + 8 * 72);
            qh[2] = *(const u32*)(QhS + aoff + 8);
            qh[3] = *(const u32*)(QhS + aoff + 8 * 72 + 8);
            ql[0] = *(const u32*)(QlS + aoff);
            ql[1] = *(const u32*)(QlS + aoff + 8 * 72);
            ql[2] = *(const u32*)(QlS + aoff + 8);
            ql[3] = *(const u32*)(QlS + aoff + 8 * 72 + 8);
            #pragma unroll
            for (int n = 0; n < 16; n++) {
                const int boff = (n * 8 + ln4) * 72 + k * 16 + (lm4 << 1);
                u32 bhh[2], bll[2];
                bhh[0] = *(const u32*)(KhS + boff);
                bhh[1] = *(const u32*)(KhS + boff + 8);
                bll[0] = *(const u32*)(KlS + boff);
                bll[1] = *(const u32*)(KlS + boff + 8);
                mma_bf16(c[n], qh, bhh);
                mma_bf16(c[n], ql, bhh);
                mma_bf16(c[n], qh, bll);
            }
        }

        // ---- bias + exp (no max shift; scores bounded) + pack P frags --------
        u32 Ah[8][4], Al[8][4];
        #pragma unroll
        for (int n = 0; n < 16; n++) {
            const int jb = j0 + n * 8 + (lm4 << 1);
            int t0 = (n0 + r0) - jb + 512;
            int ta = t0 < 0 ? 0 : (t0 > 1024 ? 1024 : t0);
            int t1 = t0 - 1;
            int tb = t1 < 0 ? 0 : (t1 > 1024 ? 1024 : t1);
            int t2 = t0 + 8;
            int tc = t2 < 0 ? 0 : (t2 > 1024 ? 1024 : t2);
            int t3 = t0 + 7;
            int td = t3 < 0 ? 0 : (t3 > 1024 ? 1024 : t3);
            float p0 = __expf(c[n][0] + prow0[ta]);
            float p1 = __expf(c[n][1] + prow0[tb]);
            float p2 = __expf(c[n][2] + prow1[tc]);
            float p3 = __expf(c[n][3] + prow1[td]);
            lsum0 += p0 + p1;
            lsum1 += p2 + p3;
            c[n][0] = p0; c[n][1] = p1; c[n][2] = p2; c[n][3] = p3;
        }
        #pragma unroll
        for (int k = 0; k < 8; k++) {             // C-frag -> A-frag reuse
            bfsplit2(c[2*k][0],   c[2*k][1],   Ah[k][0], Al[k][0]);
            bfsplit2(c[2*k][2],   c[2*k][3],   Ah[k][1], Al[k][1]);
            bfsplit2(c[2*k+1][0], c[2*k+1][1], Ah[k][2], Al[k][2]);
            bfsplit2(c[2*k+1][2], c[2*k+1][3], Ah[k][3], Al[k][3]);
        }

        // ---- O += P V : k = j (8 chunks of 16), n = dd (8 chunks of 8) -------
        #pragma unroll
        for (int k = 0; k < 8; k++) {
            #pragma unroll
            for (int n = 0; n < 8; n++) {
                const int boff = (n * 8 + ln4) * 136 + k * 16 + (lm4 << 1);
                u32 vhh[2], vll[2];
                vhh[0] = *(const u32*)(VhS + boff);
                vhh[1] = *(const u32*)(VhS + boff + 8);
                vll[0] = *(const u32*)(VlS + boff);
                vll[1] = *(const u32*)(VlS + boff + 8);
                mma_bf16(o[n], Ah[k], vhh);
                mma_bf16(o[n], Al[k], vhh);
                mma_bf16(o[n], Ah[k], vll);
            }
        }
    }

    // ---- epilogue: row-sum reduce (within quad), normalize, store --------------
    lsum0 += __shfl_xor_sync(0xffffffffu, lsum0, 1);
    lsum0 += __shfl_xor_sync(0xffffffffu, lsum0, 2);
    lsum1 += __shfl_xor_sync(0xffffffffu, lsum1, 1);
    lsum1 += __shfl_xor_sync(0xffffffffu, lsum1, 2);
    const float inv0 = 1.0f / lsum0;
    const float inv1 = 1.0f / lsum1;

    float* ob0 = O + ((size_t)(b * NSEQ + n0 + r0)) * DIMM + (head << 6) + (lm4 << 1);
    float* ob1 = ob0 + 8 * DIMM;
    #pragma unroll
    for (int n = 0; n < 8; n++) {
        *(float2*)(ob0 + n * 8) = make_float2(o[n][0] * inv0, o[n][1] * inv0);
        *(float2*)(ob1 + n * 8) = make_float2(o[n][2] * inv1, o[n][3] * inv1);
    }
}

// ---------------- kernel 4: output projection + bias --------------------------------
__global__ void __launch_bounds__(256, 2) gemm_out_kernel(
    const float* __restrict__ O, const float* __restrict__ Wo,
    const float* __restrict__ bo, float* __restrict__ out)
{
    __shared__ float Ats[16][128];
    __shared__ float Bs[16][128];
    const int m0 = blockIdx.x << 7;
    const int n0 = blockIdx.y << 7;

    u64 acc[8][4] = {};
    sgemm128(O + (size_t)m0 * DIMM, DIMM, Wo + n0, DIMM, DIMM, acc, Ats, Bs);
    float s[8][8];
    unpack_acc8(acc, s);

    const int ty = threadIdx.x >> 4, tx = threadIdx.x & 15;
    const int col = n0 + (tx << 3);
    float4 b0 = *(const float4*)(bo + col);
    float4 b1 = *(const float4*)(bo + col + 4);
    #pragma unroll
    for (int ii = 0; ii < 8; ii++) {
        size_t base = (size_t)(m0 + (ty << 3) + ii) * DIMM + col;
        *(float4*)(out + base)     = make_float4(s[ii][0]+b0.x, s[ii][1]+b0.y,
                                                 s[ii][2]+b0.z, s[ii][3]+b0.w);
        *(float4*)(out + base + 4) = make_float4(s[ii][4]+b1.x, s[ii][5]+b1.y,
                                                 s[ii][6]+b1.z, s[ii][7]+b1.w);
    }
}

// ---------------- launch --------------------------------------------------------------
extern "C" void kernel_launch(void* const* d_in, const int* in_sizes, int n_in,
                              void* d_out, int out_size)
{
    const float* x   = (const float*)d_in[0];
    const float* Wq  = (const float*)d_in[1];
    const float* Wkv = (const float*)d_in[2];
    const float* Wo  = (const float*)d_in[3];
    const float* bo  = (const float*)d_in[4];
    const float* rel = (const float*)d_in[5];
    float* out = (float*)d_out;

    float *Qp, *Pp, *Op, *rTp;
    __nv_bfloat16 *Qhp, *Qlp, *Khp, *Klp, *Vhp, *Vlp;
    cudaGetSymbolAddress((void**)&Qp,  g_Q);
    cudaGetSymbolAddress((void**)&Qhp, g_Qhi);
    cudaGetSymbolAddress((void**)&Qlp, g_Qlo);
    cudaGetSymbolAddress((void**)&Khp, g_Khi);
    cudaGetSymbolAddress((void**)&Klp, g_Klo);
    cudaGetSymbolAddress((void**)&Vhp, g_Vhi);
    cudaGetSymbolAddress((void**)&Vlp, g_Vlo);
    cudaGetSymbolAddress((void**)&Pp,  g_P);
    cudaGetSymbolAddress((void**)&Op,  g_O);
    cudaGetSymbolAddress((void**)&rTp, g_relT);

    cudaFuncSetAttribute(flash_kernel,
                         cudaFuncAttributeMaxDynamicSharedMemorySize, FSM_TOTAL);

    transpose_rel_kernel<<<(DHEAD * RELTLD + 255) / 256, 256>>>(rel, rTp);
    gemm_qkv_kernel<<<dim3(MROWS / 128, 12), 256>>>(x, Wq, Wkv, Qp, Qhp, Qlp,
                                                    Khp, Klp, Vhp, Vlp);
    gemm_p_kernel<<<dim3(QROWS / 128, 9), 256>>>(Qp, rTp, Pp);
    flash_kernel<<<dim3(NSEQ / 128, BHDIM), 256, FSM_TOTAL>>>(
        Qhp, Qlp, Khp, Klp, Vhp, Vlp, Pp, Op);
    gemm_out_kernel<<<dim3(MROWS / 128, DIMM / 128), 256>>>(Op, Wo, bo, out);
}

// round 13
// speedup vs baseline: 2.0421x; 1.3627x over previous
#include <cuda_runtime.h>
#include <cuda_bf16.h>
#include <math.h>

#define BATCH   2
#define NSEQ    2048
#define HEADS   8
#define DHEAD   64
#define DIMM    512
#define BHDIM   16
#define MROWS   4096
#define QROWS   32768
#define TVALS   1025
#define PLD     1028
#define SCALE_F 0.125f

typedef unsigned long long u64;
typedef unsigned int u32;

// ---------------- device scratch ---------------------------------------------
__device__ __nv_bfloat16 g_xhi[MROWS * DIMM];         // [m][k]
__device__ __nv_bfloat16 g_xlo[MROWS * DIMM];
__device__ __nv_bfloat16 g_Wthi[1536 * DIMM];         // [c][k]  (Wq|Wkv transposed)
__device__ __nv_bfloat16 g_Wtlo[1536 * DIMM];
__device__ __nv_bfloat16 g_WoThi[DIMM * DIMM];        // [c][k]  (Wo transposed)
__device__ __nv_bfloat16 g_WoTlo[DIMM * DIMM];
__device__ __nv_bfloat16 g_relhi[1152 * DHEAD];       // [t][d] zero-padded
__device__ __nv_bfloat16 g_rello[1152 * DHEAD];
__device__ __nv_bfloat16 g_Qhi[QROWS * DHEAD];        // [bh][n][d] scaled
__device__ __nv_bfloat16 g_Qlo[QROWS * DHEAD];
__device__ __nv_bfloat16 g_Khi[QROWS * DHEAD];        // [bh][n][d]
__device__ __nv_bfloat16 g_Klo[QROWS * DHEAD];
__device__ __nv_bfloat16 g_Vhi[QROWS * DHEAD];        // [bh][d][n]
__device__ __nv_bfloat16 g_Vlo[QROWS * DHEAD];
__device__ __nv_bfloat16 g_Ohi[MROWS * DIMM];         // [m][h*d]
__device__ __nv_bfloat16 g_Olo[MROWS * DIMM];
__device__ float g_P [(size_t)QROWS * PLD];

// ---------------- bf16 split helpers -------------------------------------------
__device__ __forceinline__ void bfsplit2(float f0, float f1, u32& hi, u32& lo) {
    __nv_bfloat16 h0 = __float2bfloat16(f0), h1 = __float2bfloat16(f1);
    __nv_bfloat16 g0 = __float2bfloat16(f0 - __bfloat162float(h0));
    __nv_bfloat16 g1 = __float2bfloat16(f1 - __bfloat162float(h1));
    hi = (u32)__bfloat16_as_ushort(h0) | ((u32)__bfloat16_as_ushort(h1) << 16);
    lo = (u32)__bfloat16_as_ushort(g0) | ((u32)__bfloat16_as_ushort(g1) << 16);
}
__device__ __forceinline__ void bfsplit1(float f, __nv_bfloat16& h, __nv_bfloat16& l) {
    h = __float2bfloat16(f);
    l = __float2bfloat16(f - __bfloat162float(h));
}

// ---------------- cp.async -------------------------------------------------------
__device__ __forceinline__ void cp16s(u32 dst, const void* src) {
    asm volatile("cp.async.ca.shared.global [%0], [%1], 16;" :: "r"(dst), "l"(src));
}
#define CP_COMMIT() asm volatile("cp.async.commit_group;")
#define CP_WAIT0()  asm volatile("cp.async.wait_group 0;")

__device__ __forceinline__ u32 smem_u32(const void* p) {
    u32 a;
    asm("{ .reg .u64 t; cvta.to.shared.u64 t, %1; cvt.u32.u64 %0, t; }" : "=r"(a) : "l"(p));
    return a;
}

// ---------------- HMMA m16n8k16 bf16 ---------------------------------------------
__device__ __forceinline__ void mma_bf16(float* d, const u32* a, const u32* b) {
    asm volatile(
        "mma.sync.aligned.m16n8k16.row.col.f32.bf16.bf16.f32 "
        "{%0,%1,%2,%3}, {%4,%5,%6,%7}, {%8,%9}, {%0,%1,%2,%3};"
        : "+f"(d[0]), "+f"(d[1]), "+f"(d[2]), "+f"(d[3])
        : "r"(a[0]), "r"(a[1]), "r"(a[2]), "r"(a[3]), "r"(b[0]), "r"(b[1]));
}

// ================= shared HMMA GEMM core ==========================================
// C[128x128] = A[128xK] * B[128xK]^T, 3-term split-bf16. 256 threads (8 warps),
// warp w -> rows 16w..16w+15, all 128 cols. K in chunks of 64, cp.async dbl-buffer.
// smem per buffer: AH/AL/BH/BL each 128 rows x 72 bf16 (144B) = 18432B -> 73728B.
#define GB_STRIDE 73728
#define GSM_DBL   147456
#define GSM_SGL   73728

__device__ __forceinline__ void hmma_stage(
    u32 smb, int buf, int k0, int tid,
    const __nv_bfloat16* Ah, const __nv_bfloat16* Al, int lda,
    const __nv_bfloat16* Bh, const __nv_bfloat16* Bl, int ldb)
{
    u32 base = smb + (u32)buf * GB_STRIDE;
    #pragma unroll
    for (int q = 0; q < 4; q++) {
        int idx = (q << 8) + tid;
        int r = idx >> 3, ch = idx & 7;
        u32 off = (u32)(r * 144 + ch * 16);
        size_t sa = (size_t)r * lda + k0 + ch * 8;
        size_t sb = (size_t)r * ldb + k0 + ch * 8;
        cp16s(base + off,         Ah + sa);
        cp16s(base + 18432 + off, Al + sa);
        cp16s(base + 36864 + off, Bh + sb);
        cp16s(base + 55296 + off, Bl + sb);
    }
}

__device__ __forceinline__ void hmma_core(
    u32 smb, const char* smc,
    const __nv_bfloat16* Ah, const __nv_bfloat16* Al, int lda,
    const __nv_bfloat16* Bh, const __nv_bfloat16* Bl, int ldb,
    int kdim, float (&c)[16][4])
{
    const int tid = threadIdx.x;
    const int wid = tid >> 5, lane = tid & 31;
    const int ln4 = lane >> 2, lm4 = lane & 3;
    const int r0 = (wid << 4) + ln4;

    #pragma unroll
    for (int n = 0; n < 16; n++)
        #pragma unroll
        for (int p = 0; p < 4; p++) c[n][p] = 0.0f;

    hmma_stage(smb, 0, 0, tid, Ah, Al, lda, Bh, Bl, ldb);
    CP_COMMIT();

    const int nchunks = kdim >> 6;
    for (int kc = 0; kc < nchunks; kc++) {
        CP_WAIT0();
        __syncthreads();
        if (kc + 1 < nchunks) {
            hmma_stage(smb, (kc + 1) & 1, (kc + 1) << 6, tid, Ah, Al, lda, Bh, Bl, ldb);
            CP_COMMIT();
        }
        const char* bufp = smc + (size_t)(kc & 1) * GB_STRIDE;
        const __nv_bfloat16* AhS = (const __nv_bfloat16*)(bufp);
        const __nv_bfloat16* AlS = (const __nv_bfloat16*)(bufp + 18432);
        const __nv_bfloat16* BhS = (const __nv_bfloat16*)(bufp + 36864);
        const __nv_bfloat16* BlS = (const __nv_bfloat16*)(bufp + 55296);

        #pragma unroll
        for (int k = 0; k < 4; k++) {
            const int aoff = r0 * 72 + k * 16 + (lm4 << 1);
            u32 ah[4], al[4];
            ah[0] = *(const u32*)(AhS + aoff);
            ah[1] = *(const u32*)(AhS + aoff + 8 * 72);
            ah[2] = *(const u32*)(AhS + aoff + 8);
            ah[3] = *(const u32*)(AhS + aoff + 8 * 72 + 8);
            al[0] = *(const u32*)(AlS + aoff);
            al[1] = *(const u32*)(AlS + aoff + 8 * 72);
            al[2] = *(const u32*)(AlS + aoff + 8);
            al[3] = *(const u32*)(AlS + aoff + 8 * 72 + 8);
            #pragma unroll
            for (int n = 0; n < 16; n++) {
                const int boff = (n * 8 + ln4) * 72 + k * 16 + (lm4 << 1);
                u32 bh2[2], bl2[2];
                bh2[0] = *(const u32*)(BhS + boff);
                bh2[1] = *(const u32*)(BhS + boff + 8);
                bl2[0] = *(const u32*)(BlS + boff);
                bl2[1] = *(const u32*)(BlS + boff + 8);
                mma_bf16(c[n], ah, bh2);
                mma_bf16(c[n], al, bh2);
                mma_bf16(c[n], ah, bl2);
            }
        }
        __syncthreads();
    }
}

// ================= split prepasses =================================================
__global__ void __launch_bounds__(256) split_x_kernel(
    const float* __restrict__ x,
    __nv_bfloat16* __restrict__ xhi, __nv_bfloat16* __restrict__ xlo)
{
    int i = blockIdx.x * 256 + threadIdx.x;          // pair index
    if (i < MROWS * DIMM / 2) {
        float2 f = *(const float2*)(x + 2 * (size_t)i);
        u32 h, l;
        bfsplit2(f.x, f.y, h, l);
        *(u32*)(xhi + 2 * (size_t)i) = h;
        *(u32*)(xlo + 2 * (size_t)i) = l;
    }
}

__global__ void __launch_bounds__(256) split_w_kernel(
    const float* __restrict__ Wq, const float* __restrict__ Wkv,
    const float* __restrict__ Wo,
    __nv_bfloat16* __restrict__ Wthi, __nv_bfloat16* __restrict__ Wtlo,
    __nv_bfloat16* __restrict__ WoThi, __nv_bfloat16* __restrict__ WoTlo)
{
    int idx = blockIdx.x * 256 + threadIdx.x;
    if (idx < 1536 * 256) {
        int c = idx >> 8, k = (idx & 255) << 1;
        float f0, f1;
        if (c < 512) { f0 = Wq[(size_t)k * 512 + c];  f1 = Wq[(size_t)(k+1) * 512 + c]; }
        else { f0 = Wkv[(size_t)k * 1024 + c - 512]; f1 = Wkv[(size_t)(k+1) * 1024 + c - 512]; }
        u32 h, l;
        bfsplit2(f0, f1, h, l);
        *(u32*)(Wthi + (size_t)c * 512 + k) = h;
        *(u32*)(Wtlo + (size_t)c * 512 + k) = l;
    } else if (idx < 1536 * 256 + 512 * 256) {
        int j = idx - 1536 * 256;
        int c = j >> 8, k = (j & 255) << 1;
        float f0 = Wo[(size_t)k * 512 + c], f1 = Wo[(size_t)(k+1) * 512 + c];
        u32 h, l;
        bfsplit2(f0, f1, h, l);
        *(u32*)(WoThi + (size_t)c * 512 + k) = h;
        *(u32*)(WoTlo + (size_t)c * 512 + k) = l;
    }
}

__global__ void __launch_bounds__(256) split_rel_kernel(
    const float* __restrict__ rel,
    __nv_bfloat16* __restrict__ relhi, __nv_bfloat16* __restrict__ rello)
{
    int idx = blockIdx.x * 256 + threadIdx.x;        // pair index over 1152x32
    if (idx < 1152 * 32) {
        int t = idx >> 5, dp = (idx & 31) << 1;
        float f0 = 0.0f, f1 = 0.0f;
        if (t < TVALS) {
            f0 = rel[(size_t)t * DHEAD + dp];
            f1 = rel[(size_t)t * DHEAD + dp + 1];
        }
        u32 h, l;
        bfsplit2(f0, f1, h, l);
        *(u32*)(relhi + (size_t)t * DHEAD + dp) = h;
        *(u32*)(rello + (size_t)t * DHEAD + dp) = l;
    }
}

// ================= kernel 1: QKV projection (HMMA) =================================
__global__ void __launch_bounds__(256, 1) qkv_hmma_kernel(
    const __nv_bfloat16* __restrict__ xhi, const __nv_bfloat16* __restrict__ xlo,
    const __nv_bfloat16* __restrict__ Wthi, const __nv_bfloat16* __restrict__ Wtlo,
    __nv_bfloat16* __restrict__ Qhi, __nv_bfloat16* __restrict__ Qlo,
    __nv_bfloat16* __restrict__ Khi, __nv_bfloat16* __restrict__ Klo,
    __nv_bfloat16* __restrict__ Vhi, __nv_bfloat16* __restrict__ Vlo)
{
    extern __shared__ char smc[];
    const u32 smb = smem_u32(smc);
    const int m0 = blockIdx.x << 7;
    const int c0 = blockIdx.y << 7;

    float c[16][4];
    hmma_core(smb, smc, xhi + (size_t)m0 * DIMM, xlo + (size_t)m0 * DIMM, DIMM,
              Wthi + (size_t)c0 * DIMM, Wtlo + (size_t)c0 * DIMM, DIMM, DIMM, c);

    const int tid = threadIdx.x, wid = tid >> 5, lane = tid & 31;
    const int ln4 = lane >> 2, lm4 = lane & 3;
    const int b = m0 >> 11;
    const int ns0 = (m0 & 2047) + (wid << 4) + ln4;   // seq row, +8 for upper half

    if (c0 < 1024) {
        // Q (scaled) or K -> [bh][n][d] bf16 hi/lo
        const float sc = (c0 < 512) ? SCALE_F : 1.0f;
        __nv_bfloat16* Dh = (c0 < 512) ? Qhi : Khi;
        __nv_bfloat16* Dl = (c0 < 512) ? Qlo : Klo;
        #pragma unroll
        for (int n = 0; n < 16; n++) {
            int col = (c0 & 511) + n * 8 + (lm4 << 1);
            int head = col >> 6, dl = col & 63;
            size_t base0 = (((size_t)(b * HEADS + head)) * NSEQ + ns0) * DHEAD + dl;
            size_t base1 = base0 + 8 * DHEAD;
            u32 h, l;
            bfsplit2(c[n][0] * sc, c[n][1] * sc, h, l);
            *(u32*)(Dh + base0) = h; *(u32*)(Dl + base0) = l;
            bfsplit2(c[n][2] * sc, c[n][3] * sc, h, l);
            *(u32*)(Dh + base1) = h; *(u32*)(Dl + base1) = l;
        }
    } else {
        // V -> [bh][d][n] transposed, scalar bf16 stores
        #pragma unroll
        for (int n = 0; n < 16; n++) {
            int col = (c0 - 1024) + n * 8 + (lm4 << 1);
            int head = col >> 6, d0 = col & 63;
            size_t rowbase = ((size_t)(b * HEADS + head) * DHEAD + d0) * NSEQ;
            #pragma unroll
            for (int e = 0; e < 2; e++) {
                __nv_bfloat16 h, l;
                bfsplit1(c[n][e], h, l);
                Vhi[rowbase + (size_t)e * NSEQ + ns0] = h;
                Vlo[rowbase + (size_t)e * NSEQ + ns0] = l;
                bfsplit1(c[n][2 + e], h, l);
                Vhi[rowbase + (size_t)e * NSEQ + ns0 + 8] = h;
                Vlo[rowbase + (size_t)e * NSEQ + ns0 + 8] = l;
            }
        }
    }
}

// ================= kernel 2: P = Qscaled @ rel^T (HMMA, K=64) =======================
__global__ void __launch_bounds__(256, 1) p_hmma_kernel(
    const __nv_bfloat16* __restrict__ Qhi, const __nv_bfloat16* __restrict__ Qlo,
    const __nv_bfloat16* __restrict__ relhi, const __nv_bfloat16* __restrict__ rello,
    float* __restrict__ P)
{
    extern __shared__ char smc[];
    const u32 smb = smem_u32(smc);
    const int m0 = blockIdx.x << 7;
    const int t0 = blockIdx.y << 7;

    float c[16][4];
    hmma_core(smb, smc, Qhi + (size_t)m0 * DHEAD, Qlo + (size_t)m0 * DHEAD, DHEAD,
              relhi + (size_t)t0 * DHEAD, rello + (size_t)t0 * DHEAD, DHEAD, DHEAD, c);

    const int tid = threadIdx.x, wid = tid >> 5, lane = tid & 31;
    const int ln4 = lane >> 2, lm4 = lane & 3;
    const size_t r0 = m0 + (wid << 4) + ln4;

    #pragma unroll
    for (int n = 0; n < 16; n++) {
        int col = t0 + n * 8 + (lm4 << 1);
        if (col + 1 < TVALS) {
            *(float2*)(P + r0 * PLD + col) = make_float2(c[n][0], c[n][1]);
            *(float2*)(P + (r0 + 8) * PLD + col) = make_float2(c[n][2], c[n][3]);
        } else if (col < TVALS) {
            P[r0 * PLD + col] = c[n][0];
            P[(r0 + 8) * PLD + col] = c[n][2];
        }
    }
}

// ================= kernel 3: HMMA flash attention ===================================
#define FQH  0
#define FQL  18432
#define FKH0 36864
#define FKL0 55296
#define FKH1 73728
#define FKL1 92160
#define FVH0 110592
#define FVL0 128000
#define FVH1 145408
#define FVL1 162816
#define FSM_TOTAL 180224

__device__ __forceinline__ void stage_kv_tile(
    u32 smb, int buf, int j0, int tid,
    const __nv_bfloat16* Kh, const __nv_bfloat16* Kl,
    const __nv_bfloat16* Vh, const __nv_bfloat16* Vl)
{
    u32 kh = smb + (buf ? FKH1 : FKH0);
    u32 kl = smb + (buf ? FKL1 : FKL0);
    u32 vh = smb + (buf ? FVH1 : FVH0);
    u32 vl = smb + (buf ? FVL1 : FVL0);
    #pragma unroll
    for (int q = 0; q < 4; q++) {
        int idx = (q << 8) + tid;
        int r = idx >> 3, ch = idx & 7;
        u32 off = (u32)(r * 144 + ch * 16);
        size_t src = (size_t)(j0 + r) * DHEAD + ch * 8;
        cp16s(kh + off, Kh + src);
        cp16s(kl + off, Kl + src);
    }
    #pragma unroll
    for (int q = 0; q < 4; q++) {
        int idx = (q << 8) + tid;
        int d = idx >> 4, ch = idx & 15;
        u32 off = (u32)(d * 272 + ch * 16);
        size_t src = (size_t)d * NSEQ + j0 + ch * 8;
        cp16s(vh + off, Vh + src);
        cp16s(vl + off, Vl + src);
    }
}

__global__ void __launch_bounds__(256, 1) flash_kernel(
    const __nv_bfloat16* __restrict__ Qhi, const __nv_bfloat16* __restrict__ Qlo,
    const __nv_bfloat16* __restrict__ Khi, const __nv_bfloat16* __restrict__ Klo,
    const __nv_bfloat16* __restrict__ Vhi, const __nv_bfloat16* __restrict__ Vlo,
    const float* __restrict__ P,
    __nv_bfloat16* __restrict__ Ohi, __nv_bfloat16* __restrict__ Olo)
{
    extern __shared__ char smc[];
    const u32 smb = smem_u32(smc);
    const __nv_bfloat16* QhS = (const __nv_bfloat16*)(smc + FQH);
    const __nv_bfloat16* QlS = (const __nv_bfloat16*)(smc + FQL);

    const int tid  = threadIdx.x;
    const int wid  = tid >> 5, lane = tid & 31;
    const int ln4  = lane >> 2;
    const int lm4  = lane & 3;
    const int bh   = blockIdx.y, n0 = blockIdx.x << 7;
    const int b    = bh >> 3, head = bh & 7;

    const __nv_bfloat16* Qhg = Qhi + ((size_t)bh * NSEQ + n0) * DHEAD;
    const __nv_bfloat16* Qlg = Qlo + ((size_t)bh * NSEQ + n0) * DHEAD;
    const __nv_bfloat16* Khg = Khi + (size_t)bh * NSEQ * DHEAD;
    const __nv_bfloat16* Klg = Klo + (size_t)bh * NSEQ * DHEAD;
    const __nv_bfloat16* Vhg = Vhi + (size_t)bh * DHEAD * NSEQ;
    const __nv_bfloat16* Vlg = Vlo + (size_t)bh * DHEAD * NSEQ;

    #pragma unroll
    for (int q = 0; q < 4; q++) {
        int idx = (q << 8) + tid;
        int r = idx >> 3, ch = idx & 7;
        u32 off = (u32)(r * 144 + ch * 16);
        size_t src = (size_t)r * DHEAD + ch * 8;
        cp16s(smb + FQH + off, Qhg + src);
        cp16s(smb + FQL + off, Qlg + src);
    }
    stage_kv_tile(smb, 0, 0, tid, Khg, Klg, Vhg, Vlg);
    CP_COMMIT();

    const int r0 = (wid << 4) + ln4;
    const float* prow0 = P + ((size_t)bh * NSEQ + n0 + r0) * PLD;
    const float* prow1 = prow0 + 8 * PLD;

    float o[8][4];
    #pragma unroll
    for (int n = 0; n < 8; n++)
        #pragma unroll
        for (int p = 0; p < 4; p++) o[n][p] = 0.0f;
    float lsum0 = 0.0f, lsum1 = 0.0f;

    for (int jt = 0; jt < 16; jt++) {
        const int j0 = jt << 7;
        const int buf = jt & 1;
        const __nv_bfloat16* KhS = (const __nv_bfloat16*)(smc + (buf ? FKH1 : FKH0));
        const __nv_bfloat16* KlS = (const __nv_bfloat16*)(smc + (buf ? FKL1 : FKL0));
        const __nv_bfloat16* VhS = (const __nv_bfloat16*)(smc + (buf ? FVH1 : FVH0));
        const __nv_bfloat16* VlS = (const __nv_bfloat16*)(smc + (buf ? FVL1 : FVL0));

        CP_WAIT0();
        __syncthreads();

        if (jt + 1 < 16)
            stage_kv_tile(smb, buf ^ 1, j0 + 128, tid, Khg, Klg, Vhg, Vlg);
        CP_COMMIT();

        float c[16][4];
        #pragma unroll
        for (int n = 0; n < 16; n++)
            #pragma unroll
            for (int p = 0; p < 4; p++) c[n][p] = 0.0f;

        #pragma unroll
        for (int k = 0; k < 4; k++) {
            const int aoff = r0 * 72 + k * 16 + (lm4 << 1);
            u32 qh[4], ql[4];
            qh[0] = *(const u32*)(QhS + aoff);
            qh[1] = *(const u32*)(QhS + aoff + 8 * 72);
            qh[2] = *(const u32*)(QhS + aoff + 8);
            qh[3] = *(const u32*)(QhS + aoff + 8 * 72 + 8);
            ql[0] = *(const u32*)(QlS + aoff);
            ql[1] = *(const u32*)(QlS + aoff + 8 * 72);
            ql[2] = *(const u32*)(QlS + aoff + 8);
            ql[3] = *(const u32*)(QlS + aoff + 8 * 72 + 8);
            #pragma unroll
            for (int n = 0; n < 16; n++) {
                const int boff = (n * 8 + ln4) * 72 + k * 16 + (lm4 << 1);
                u32 bhh[2], bll[2];
                bhh[0] = *(const u32*)(KhS + boff);
                bhh[1] = *(const u32*)(KhS + boff + 8);
                bll[0] = *(const u32*)(KlS + boff);
                bll[1] = *(const u32*)(KlS + boff + 8);
                mma_bf16(c[n], qh, bhh);
                mma_bf16(c[n], ql, bhh);
                mma_bf16(c[n], qh, bll);
            }
        }

        u32 Ah[8][4], Al[8][4];
        #pragma unroll
        for (int n = 0; n < 16; n++) {
            const int jb = j0 + n * 8 + (lm4 << 1);
            int t0 = (n0 + r0) - jb + 512;
            int ta = t0 < 0 ? 0 : (t0 > 1024 ? 1024 : t0);
            int t1 = t0 - 1;
            int tb = t1 < 0 ? 0 : (t1 > 1024 ? 1024 : t1);
            int t2 = t0 + 8;
            int tc = t2 < 0 ? 0 : (t2 > 1024 ? 1024 : t2);
            int t3 = t0 + 7;
            int td = t3 < 0 ? 0 : (t3 > 1024 ? 1024 : t3);
            float p0 = __expf(c[n][0] + prow0[ta]);
            float p1 = __expf(c[n][1] + prow0[tb]);
            float p2 = __expf(c[n][2] + prow1[tc]);
            float p3 = __expf(c[n][3] + prow1[td]);
            lsum0 += p0 + p1;
            lsum1 += p2 + p3;
            c[n][0] = p0; c[n][1] = p1; c[n][2] = p2; c[n][3] = p3;
        }
        #pragma unroll
        for (int k = 0; k < 8; k++) {
            bfsplit2(c[2*k][0],   c[2*k][1],   Ah[k][0], Al[k][0]);
            bfsplit2(c[2*k][2],   c[2*k][3],   Ah[k][1], Al[k][1]);
            bfsplit2(c[2*k+1][0], c[2*k+1][1], Ah[k][2], Al[k][2]);
            bfsplit2(c[2*k+1][2], c[2*k+1][3], Ah[k][3], Al[k][3]);
        }

        #pragma unroll
        for (int k = 0; k < 8; k++) {
            #pragma unroll
            for (int n = 0; n < 8; n++) {
                const int boff = (n * 8 + ln4) * 136 + k * 16 + (lm4 << 1);
                u32 vhh[2], vll[2];
                vhh[0] = *(const u32*)(VhS + boff);
                vhh[1] = *(const u32*)(VhS + boff + 8);
                vll[0] = *(const u32*)(VlS + boff);
                vll[1] = *(const u32*)(VlS + boff + 8);
                mma_bf16(o[n], Ah[k], vhh);
                mma_bf16(o[n], Al[k], vhh);
                mma_bf16(o[n], Ah[k], vll);
            }
        }
    }

    lsum0 += __shfl_xor_sync(0xffffffffu, lsum0, 1);
    lsum0 += __shfl_xor_sync(0xffffffffu, lsum0, 2);
    lsum1 += __shfl_xor_sync(0xffffffffu, lsum1, 1);
    lsum1 += __shfl_xor_sync(0xffffffffu, lsum1, 2);
    const float inv0 = 1.0f / lsum0;
    const float inv1 = 1.0f / lsum1;

    size_t ob0 = ((size_t)(b * NSEQ + n0 + r0)) * DIMM + (head << 6) + (lm4 << 1);
    size_t ob1 = ob0 + 8 * DIMM;
    #pragma unroll
    for (int n = 0; n < 8; n++) {
        u32 h, l;
        bfsplit2(o[n][0] * inv0, o[n][1] * inv0, h, l);
        *(u32*)(Ohi + ob0 + n * 8) = h;
        *(u32*)(Olo + ob0 + n * 8) = l;
        bfsplit2(o[n][2] * inv1, o[n][3] * inv1, h, l);
        *(u32*)(Ohi + ob1 + n * 8) = h;
        *(u32*)(Olo + ob1 + n * 8) = l;
    }
}

// ================= kernel 4: output projection (HMMA) ==============================
__global__ void __launch_bounds__(256, 1) out_hmma_kernel(
    const __nv_bfloat16* __restrict__ Ohi, const __nv_bfloat16* __restrict__ Olo,
    const __nv_bfloat16* __restrict__ WoThi, const __nv_bfloat16* __restrict__ WoTlo,
    const float* __restrict__ bo, float* __restrict__ out)
{
    extern __shared__ char smc[];
    const u32 smb = smem_u32(smc);
    const int m0 = blockIdx.x << 7;
    const int c0 = blockIdx.y << 7;

    float c[16][4];
    hmma_core(smb, smc, Ohi + (size_t)m0 * DIMM, Olo + (size_t)m0 * DIMM, DIMM,
              WoThi + (size_t)c0 * DIMM, WoTlo + (size_t)c0 * DIMM, DIMM, DIMM, c);

    const int tid = threadIdx.x, wid = tid >> 5, lane = tid & 31;
    const int ln4 = lane >> 2, lm4 = lane & 3;
    const size_t r0 = m0 + (wid << 4) + ln4;

    #pragma unroll
    for (int n = 0; n < 16; n++) {
        int col = c0 + n * 8 + (lm4 << 1);
        float2 bb = *(const float2*)(bo + col);
        *(float2*)(out + r0 * DIMM + col) = make_float2(c[n][0] + bb.x, c[n][1] + bb.y);
        *(float2*)(out + (r0 + 8) * DIMM + col) = make_float2(c[n][2] + bb.x, c[n][3] + bb.y);
    }
}

// ================= launch ==========================================================
extern "C" void kernel_launch(void* const* d_in, const int* in_sizes, int n_in,
                              void* d_out, int out_size)
{
    const float* x   = (const float*)d_in[0];
    const float* Wq  = (const float*)d_in[1];
    const float* Wkv = (const float*)d_in[2];
    const float* Wo  = (const float*)d_in[3];
    const float* bo  = (const float*)d_in[4];
    const float* rel = (const float*)d_in[5];
    float* out = (float*)d_out;

    __nv_bfloat16 *xh, *xl, *wth, *wtl, *woh, *wol, *rh, *rl;
    __nv_bfloat16 *qh, *ql, *kh, *kl, *vh, *vl, *oh, *ol;
    float *Pp;
    cudaGetSymbolAddress((void**)&xh,  g_xhi);
    cudaGetSymbolAddress((void**)&xl,  g_xlo);
    cudaGetSymbolAddress((void**)&wth, g_Wthi);
    cudaGetSymbolAddress((void**)&wtl, g_Wtlo);
    cudaGetSymbolAddress((void**)&woh, g_WoThi);
    cudaGetSymbolAddress((void**)&wol, g_WoTlo);
    cudaGetSymbolAddress((void**)&rh,  g_relhi);
    cudaGetSymbolAddress((void**)&rl,  g_rello);
    cudaGetSymbolAddress((void**)&qh,  g_Qhi);
    cudaGetSymbolAddress((void**)&ql,  g_Qlo);
    cudaGetSymbolAddress((void**)&kh,  g_Khi);
    cudaGetSymbolAddress((void**)&kl,  g_Klo);
    cudaGetSymbolAddress((void**)&vh,  g_Vhi);
    cudaGetSymbolAddress((void**)&vl,  g_Vlo);
    cudaGetSymbolAddress((void**)&oh,  g_Ohi);
    cudaGetSymbolAddress((void**)&ol,  g_Olo);
    cudaGetSymbolAddress((void**)&Pp,  g_P);

    cudaFuncSetAttribute(qkv_hmma_kernel,
                         cudaFuncAttributeMaxDynamicSharedMemorySize, GSM_DBL);
    cudaFuncSetAttribute(p_hmma_kernel,
                         cudaFuncAttributeMaxDynamicSharedMemorySize, GSM_SGL);
    cudaFuncSetAttribute(out_hmma_kernel,
                         cudaFuncAttributeMaxDynamicSharedMemorySize, GSM_DBL);
    cudaFuncSetAttribute(flash_kernel,
                         cudaFuncAttributeMaxDynamicSharedMemorySize, FSM_TOTAL);

    split_x_kernel<<<MROWS * DIMM / 512, 256>>>(x, xh, xl);
    split_w_kernel<<<2048, 256>>>(Wq, Wkv, Wo, wth, wtl, woh, wol);
    split_rel_kernel<<<144, 256>>>(rel, rh, rl);

    qkv_hmma_kernel<<<dim3(32, 12), 256, GSM_DBL>>>(xh, xl, wth, wtl,
                                                    qh, ql, kh, kl, vh, vl);
    p_hmma_kernel<<<dim3(256, 9), 256, GSM_SGL>>>(qh, ql, rh, rl, Pp);
    flash_kernel<<<dim3(16, 16), 256, FSM_TOTAL>>>(qh, ql, kh, kl, vh, vl, Pp, oh, ol);
    out_hmma_kernel<<<dim3(32, 4), 256, GSM_DBL>>>(oh, ol, woh, wol, bo, out);
}

// round 14
// speedup vs baseline: 2.1289x; 1.0425x over previous
#include <cuda_runtime.h>
#include <cuda_bf16.h>
#include <math.h>

#define BATCH   2
#define NSEQ    2048
#define HEADS   8
#define DHEAD   64
#define DIMM    512
#define BHDIM   16
#define MROWS   4096
#define QROWS   32768
#define TVALS   1025
#define PLD     1028
#define SCALE_F 0.125f

typedef unsigned long long u64;
typedef unsigned int u32;

// ---------------- device scratch ---------------------------------------------
__device__ __nv_bfloat16 g_xhi[MROWS * DIMM];         // [m][k]
__device__ __nv_bfloat16 g_xlo[MROWS * DIMM];
__device__ __nv_bfloat16 g_Wthi[1536 * DIMM];         // [c][k]
__device__ __nv_bfloat16 g_Wtlo[1536 * DIMM];
__device__ __nv_bfloat16 g_WoThi[DIMM * DIMM];        // [c][k]
__device__ __nv_bfloat16 g_WoTlo[DIMM * DIMM];
__device__ __nv_bfloat16 g_relhi[1152 * DHEAD];       // [t][d] zero-padded
__device__ __nv_bfloat16 g_rello[1152 * DHEAD];
__device__ __nv_bfloat16 g_Qhi[QROWS * DHEAD];        // [bh][n][d] scaled
__device__ __nv_bfloat16 g_Qlo[QROWS * DHEAD];
__device__ __nv_bfloat16 g_Khi[QROWS * DHEAD];        // [bh][n][d]
__device__ __nv_bfloat16 g_Klo[QROWS * DHEAD];
__device__ __nv_bfloat16 g_Vhi[QROWS * DHEAD];        // [bh][d][n]
__device__ __nv_bfloat16 g_Vlo[QROWS * DHEAD];
__device__ __nv_bfloat16 g_Ohi[MROWS * DIMM];         // [m][h*d]
__device__ __nv_bfloat16 g_Olo[MROWS * DIMM];
__device__ float g_P [(size_t)QROWS * PLD];

// ---------------- bf16 split helpers -------------------------------------------
__device__ __forceinline__ void bfsplit2(float f0, float f1, u32& hi, u32& lo) {
    __nv_bfloat16 h0 = __float2bfloat16(f0), h1 = __float2bfloat16(f1);
    __nv_bfloat16 g0 = __float2bfloat16(f0 - __bfloat162float(h0));
    __nv_bfloat16 g1 = __float2bfloat16(f1 - __bfloat162float(h1));
    hi = (u32)__bfloat16_as_ushort(h0) | ((u32)__bfloat16_as_ushort(h1) << 16);
    lo = (u32)__bfloat16_as_ushort(g0) | ((u32)__bfloat16_as_ushort(g1) << 16);
}
__device__ __forceinline__ void bfsplit1(float f, __nv_bfloat16& h, __nv_bfloat16& l) {
    h = __float2bfloat16(f);
    l = __float2bfloat16(f - __bfloat162float(h));
}

// ---------------- cp.async -------------------------------------------------------
__device__ __forceinline__ void cp16s(u32 dst, const void* src) {
    asm volatile("cp.async.ca.shared.global [%0], [%1], 16;" :: "r"(dst), "l"(src));
}
#define CP_COMMIT() asm volatile("cp.async.commit_group;")
#define CP_WAIT0()  asm volatile("cp.async.wait_group 0;")

__device__ __forceinline__ u32 smem_u32(const void* p) {
    u32 a;
    asm("{ .reg .u64 t; cvta.to.shared.u64 t, %1; cvt.u32.u64 %0, t; }" : "=r"(a) : "l"(p));
    return a;
}

// ---------------- HMMA m16n8k16 bf16 ---------------------------------------------
__device__ __forceinline__ void mma_bf16(float* d, const u32* a, const u32* b) {
    asm volatile(
        "mma.sync.aligned.m16n8k16.row.col.f32.bf16.bf16.f32 "
        "{%0,%1,%2,%3}, {%4,%5,%6,%7}, {%8,%9}, {%0,%1,%2,%3};"
        : "+f"(d[0]), "+f"(d[1]), "+f"(d[2]), "+f"(d[3])
        : "r"(a[0]), "r"(a[1]), "r"(a[2]), "r"(a[3]), "r"(b[0]), "r"(b[1]));
}

// ================= shared HMMA GEMM core (single-buffer, 2 CTAs/SM) ===============
// C[128x128] = A[128xK] * B[128xK]^T, 3-term split-bf16. 256 threads (8 warps).
// smem: AH/AL/BH/BL each 128x72 bf16 (144B rows) = 18432B -> 73728B total.
#define GSM_SGL 73728

__device__ __forceinline__ void hmma_stage(
    u32 smb, int k0, int tid,
    const __nv_bfloat16* Ah, const __nv_bfloat16* Al, int lda,
    const __nv_bfloat16* Bh, const __nv_bfloat16* Bl, int ldb)
{
    #pragma unroll
    for (int q = 0; q < 4; q++) {
        int idx = (q << 8) + tid;
        int r = idx >> 3, ch = idx & 7;
        u32 off = (u32)(r * 144 + ch * 16);
        size_t sa = (size_t)r * lda + k0 + ch * 8;
        size_t sb = (size_t)r * ldb + k0 + ch * 8;
        cp16s(smb + off,         Ah + sa);
        cp16s(smb + 18432 + off, Al + sa);
        cp16s(smb + 36864 + off, Bh + sb);
        cp16s(smb + 55296 + off, Bl + sb);
    }
}

__device__ __forceinline__ void hmma_core(
    u32 smb, const char* smc,
    const __nv_bfloat16* Ah, const __nv_bfloat16* Al, int lda,
    const __nv_bfloat16* Bh, const __nv_bfloat16* Bl, int ldb,
    int kdim, float (&c)[16][4])
{
    const int tid = threadIdx.x;
    const int wid = tid >> 5, lane = tid & 31;
    const int ln4 = lane >> 2, lm4 = lane & 3;
    const int r0 = (wid << 4) + ln4;

    #pragma unroll
    for (int n = 0; n < 16; n++)
        #pragma unroll
        for (int p = 0; p < 4; p++) c[n][p] = 0.0f;

    hmma_stage(smb, 0, tid, Ah, Al, lda, Bh, Bl, ldb);
    CP_COMMIT();

    const __nv_bfloat16* AhS = (const __nv_bfloat16*)(smc);
    const __nv_bfloat16* AlS = (const __nv_bfloat16*)(smc + 18432);
    const __nv_bfloat16* BhS = (const __nv_bfloat16*)(smc + 36864);
    const __nv_bfloat16* BlS = (const __nv_bfloat16*)(smc + 55296);

    const int nchunks = kdim >> 6;
    for (int kc = 0; kc < nchunks; kc++) {
        CP_WAIT0();
        __syncthreads();

        #pragma unroll
        for (int k = 0; k < 4; k++) {
            const int aoff = r0 * 72 + k * 16 + (lm4 << 1);
            u32 ah[4], al[4];
            ah[0] = *(const u32*)(AhS + aoff);
            ah[1] = *(const u32*)(AhS + aoff + 8 * 72);
            ah[2] = *(const u32*)(AhS + aoff + 8);
            ah[3] = *(const u32*)(AhS + aoff + 8 * 72 + 8);
            al[0] = *(const u32*)(AlS + aoff);
            al[1] = *(const u32*)(AlS + aoff + 8 * 72);
            al[2] = *(const u32*)(AlS + aoff + 8);
            al[3] = *(const u32*)(AlS + aoff + 8 * 72 + 8);
            #pragma unroll
            for (int n = 0; n < 16; n++) {
                const int boff = (n * 8 + ln4) * 72 + k * 16 + (lm4 << 1);
                u32 bh2[2], bl2[2];
                bh2[0] = *(const u32*)(BhS + boff);
                bh2[1] = *(const u32*)(BhS + boff + 8);
                bl2[0] = *(const u32*)(BlS + boff);
                bl2[1] = *(const u32*)(BlS + boff + 8);
                mma_bf16(c[n], ah, bh2);
                mma_bf16(c[n], al, bh2);
                mma_bf16(c[n], ah, bl2);
            }
        }
        __syncthreads();
        if (kc + 1 < nchunks) {
            hmma_stage(smb, (kc + 1) << 6, tid, Ah, Al, lda, Bh, Bl, ldb);
            CP_COMMIT();
        }
    }
}

// ================= split prepasses =================================================
__global__ void __launch_bounds__(256) split_x_kernel(
    const float* __restrict__ x,
    __nv_bfloat16* __restrict__ xhi, __nv_bfloat16* __restrict__ xlo)
{
    int i = blockIdx.x * 256 + threadIdx.x;
    if (i < MROWS * DIMM / 2) {
        float2 f = *(const float2*)(x + 2 * (size_t)i);
        u32 h, l;
        bfsplit2(f.x, f.y, h, l);
        *(u32*)(xhi + 2 * (size_t)i) = h;
        *(u32*)(xlo + 2 * (size_t)i) = l;
    }
}

__global__ void __launch_bounds__(256) split_w_kernel(
    const float* __restrict__ Wq, const float* __restrict__ Wkv,
    const float* __restrict__ Wo,
    __nv_bfloat16* __restrict__ Wthi, __nv_bfloat16* __restrict__ Wtlo,
    __nv_bfloat16* __restrict__ WoThi, __nv_bfloat16* __restrict__ WoTlo)
{
    int idx = blockIdx.x * 256 + threadIdx.x;
    if (idx < 1536 * 256) {
        int c = idx >> 8, k = (idx & 255) << 1;
        float f0, f1;
        if (c < 512) { f0 = Wq[(size_t)k * 512 + c];  f1 = Wq[(size_t)(k+1) * 512 + c]; }
        else { f0 = Wkv[(size_t)k * 1024 + c - 512]; f1 = Wkv[(size_t)(k+1) * 1024 + c - 512]; }
        u32 h, l;
        bfsplit2(f0, f1, h, l);
        *(u32*)(Wthi + (size_t)c * 512 + k) = h;
        *(u32*)(Wtlo + (size_t)c * 512 + k) = l;
    } else if (idx < 1536 * 256 + 512 * 256) {
        int j = idx - 1536 * 256;
        int c = j >> 8, k = (j & 255) << 1;
        float f0 = Wo[(size_t)k * 512 + c], f1 = Wo[(size_t)(k+1) * 512 + c];
        u32 h, l;
        bfsplit2(f0, f1, h, l);
        *(u32*)(WoThi + (size_t)c * 512 + k) = h;
        *(u32*)(WoTlo + (size_t)c * 512 + k) = l;
    }
}

__global__ void __launch_bounds__(256) split_rel_kernel(
    const float* __restrict__ rel,
    __nv_bfloat16* __restrict__ relhi, __nv_bfloat16* __restrict__ rello)
{
    int idx = blockIdx.x * 256 + threadIdx.x;
    if (idx < 1152 * 32) {
        int t = idx >> 5, dp = (idx & 31) << 1;
        float f0 = 0.0f, f1 = 0.0f;
        if (t < TVALS) {
            f0 = rel[(size_t)t * DHEAD + dp];
            f1 = rel[(size_t)t * DHEAD + dp + 1];
        }
        u32 h, l;
        bfsplit2(f0, f1, h, l);
        *(u32*)(relhi + (size_t)t * DHEAD + dp) = h;
        *(u32*)(rello + (size_t)t * DHEAD + dp) = l;
    }
}

// ================= kernel 1: QKV projection (HMMA) =================================
__global__ void __launch_bounds__(256, 2) qkv_hmma_kernel(
    const __nv_bfloat16* __restrict__ xhi, const __nv_bfloat16* __restrict__ xlo,
    const __nv_bfloat16* __restrict__ Wthi, const __nv_bfloat16* __restrict__ Wtlo,
    __nv_bfloat16* __restrict__ Qhi, __nv_bfloat16* __restrict__ Qlo,
    __nv_bfloat16* __restrict__ Khi, __nv_bfloat16* __restrict__ Klo,
    __nv_bfloat16* __restrict__ Vhi, __nv_bfloat16* __restrict__ Vlo)
{
    extern __shared__ char smc[];
    const u32 smb = smem_u32(smc);
    const int m0 = blockIdx.x << 7;
    const int c0 = blockIdx.y << 7;

    float c[16][4];
    hmma_core(smb, smc, xhi + (size_t)m0 * DIMM, xlo + (size_t)m0 * DIMM, DIMM,
              Wthi + (size_t)c0 * DIMM, Wtlo + (size_t)c0 * DIMM, DIMM, DIMM, c);

    const int tid = threadIdx.x, wid = tid >> 5, lane = tid & 31;
    const int ln4 = lane >> 2, lm4 = lane & 3;
    const int b = m0 >> 11;
    const int ns0 = (m0 & 2047) + (wid << 4) + ln4;

    if (c0 < 1024) {
        const float sc = (c0 < 512) ? SCALE_F : 1.0f;
        __nv_bfloat16* Dh = (c0 < 512) ? Qhi : Khi;
        __nv_bfloat16* Dl = (c0 < 512) ? Qlo : Klo;
        #pragma unroll
        for (int n = 0; n < 16; n++) {
            int col = (c0 & 511) + n * 8 + (lm4 << 1);
            int head = col >> 6, dl = col & 63;
            size_t base0 = (((size_t)(b * HEADS + head)) * NSEQ + ns0) * DHEAD + dl;
            size_t base1 = base0 + 8 * DHEAD;
            u32 h, l;
            bfsplit2(c[n][0] * sc, c[n][1] * sc, h, l);
            *(u32*)(Dh + base0) = h; *(u32*)(Dl + base0) = l;
            bfsplit2(c[n][2] * sc, c[n][3] * sc, h, l);
            *(u32*)(Dh + base1) = h; *(u32*)(Dl + base1) = l;
        }
    } else {
        #pragma unroll
        for (int n = 0; n < 16; n++) {
            int col = (c0 - 1024) + n * 8 + (lm4 << 1);
            int head = col >> 6, d0 = col & 63;
            size_t rowbase = ((size_t)(b * HEADS + head) * DHEAD + d0) * NSEQ;
            #pragma unroll
            for (int e = 0; e < 2; e++) {
                __nv_bfloat16 h, l;
                bfsplit1(c[n][e], h, l);
                Vhi[rowbase + (size_t)e * NSEQ + ns0] = h;
                Vlo[rowbase + (size_t)e * NSEQ + ns0] = l;
                bfsplit1(c[n][2 + e], h, l);
                Vhi[rowbase + (size_t)e * NSEQ + ns0 + 8] = h;
                Vlo[rowbase + (size_t)e * NSEQ + ns0 + 8] = l;
            }
        }
    }
}

// ================= kernel 2: P = Qscaled @ rel^T (HMMA, K=64) =======================
__global__ void __launch_bounds__(256, 2) p_hmma_kernel(
    const __nv_bfloat16* __restrict__ Qhi, const __nv_bfloat16* __restrict__ Qlo,
    const __nv_bfloat16* __restrict__ relhi, const __nv_bfloat16* __restrict__ rello,
    float* __restrict__ P)
{
    extern __shared__ char smc[];
    const u32 smb = smem_u32(smc);
    const int m0 = blockIdx.x << 7;
    const int t0 = blockIdx.y << 7;

    float c[16][4];
    hmma_core(smb, smc, Qhi + (size_t)m0 * DHEAD, Qlo + (size_t)m0 * DHEAD, DHEAD,
              relhi + (size_t)t0 * DHEAD, rello + (size_t)t0 * DHEAD, DHEAD, DHEAD, c);

    const int tid = threadIdx.x, wid = tid >> 5, lane = tid & 31;
    const int ln4 = lane >> 2, lm4 = lane & 3;
    const size_t r0 = m0 + (wid << 4) + ln4;

    #pragma unroll
    for (int n = 0; n < 16; n++) {
        int col = t0 + n * 8 + (lm4 << 1);
        if (col + 1 < TVALS) {
            *(float2*)(P + r0 * PLD + col) = make_float2(c[n][0], c[n][1]);
            *(float2*)(P + (r0 + 8) * PLD + col) = make_float2(c[n][2], c[n][3]);
        } else if (col < TVALS) {
            P[r0 * PLD + col] = c[n][0];
            P[(r0 + 8) * PLD + col] = c[n][2];
        }
    }
}

// ================= kernel 3: HMMA flash attention (2 CTAs/SM) =======================
// smem: Q 36864 + K 36864 + V 34816 = 108544 B. Single-buffered K/V.
#define FQH 0
#define FQL 18432
#define FKH 36864
#define FKL 55296
#define FVH 73728
#define FVL 91136
#define FSM_TOTAL 108544

__device__ __forceinline__ void stage_kv_tile(
    u32 smb, int j0, int tid,
    const __nv_bfloat16* Kh, const __nv_bfloat16* Kl,
    const __nv_bfloat16* Vh, const __nv_bfloat16* Vl)
{
    #pragma unroll
    for (int q = 0; q < 4; q++) {
        int idx = (q << 8) + tid;
        int r = idx >> 3, ch = idx & 7;
        u32 off = (u32)(r * 144 + ch * 16);
        size_t src = (size_t)(j0 + r) * DHEAD + ch * 8;
        cp16s(smb + FKH + off, Kh + src);
        cp16s(smb + FKL + off, Kl + src);
    }
    #pragma unroll
    for (int q = 0; q < 4; q++) {
        int idx = (q << 8) + tid;
        int d = idx >> 4, ch = idx & 15;
        u32 off = (u32)(d * 272 + ch * 16);
        size_t src = (size_t)d * NSEQ + j0 + ch * 8;
        cp16s(smb + FVH + off, Vh + src);
        cp16s(smb + FVL + off, Vl + src);
    }
}

__global__ void __launch_bounds__(256, 2) flash_kernel(
    const __nv_bfloat16* __restrict__ Qhi, const __nv_bfloat16* __restrict__ Qlo,
    const __nv_bfloat16* __restrict__ Khi, const __nv_bfloat16* __restrict__ Klo,
    const __nv_bfloat16* __restrict__ Vhi, const __nv_bfloat16* __restrict__ Vlo,
    const float* __restrict__ P,
    __nv_bfloat16* __restrict__ Ohi, __nv_bfloat16* __restrict__ Olo)
{
    extern __shared__ char smc[];
    const u32 smb = smem_u32(smc);
    const __nv_bfloat16* QhS = (const __nv_bfloat16*)(smc + FQH);
    const __nv_bfloat16* QlS = (const __nv_bfloat16*)(smc + FQL);
    const __nv_bfloat16* KhS = (const __nv_bfloat16*)(smc + FKH);
    const __nv_bfloat16* KlS = (const __nv_bfloat16*)(smc + FKL);
    const __nv_bfloat16* VhS = (const __nv_bfloat16*)(smc + FVH);
    const __nv_bfloat16* VlS = (const __nv_bfloat16*)(smc + FVL);

    const int tid  = threadIdx.x;
    const int wid  = tid >> 5, lane = tid & 31;
    const int ln4  = lane >> 2;
    const int lm4  = lane & 3;
    const int bh   = blockIdx.y, n0 = blockIdx.x << 7;
    const int b    = bh >> 3, head = bh & 7;

    const __nv_bfloat16* Qhg = Qhi + ((size_t)bh * NSEQ + n0) * DHEAD;
    const __nv_bfloat16* Qlg = Qlo + ((size_t)bh * NSEQ + n0) * DHEAD;
    const __nv_bfloat16* Khg = Khi + (size_t)bh * NSEQ * DHEAD;
    const __nv_bfloat16* Klg = Klo + (size_t)bh * NSEQ * DHEAD;
    const __nv_bfloat16* Vhg = Vhi + (size_t)bh * DHEAD * NSEQ;
    const __nv_bfloat16* Vlg = Vlo + (size_t)bh * DHEAD * NSEQ;

    // stage Q (once) and K/V tile 0
    #pragma unroll
    for (int q = 0; q < 4; q++) {
        int idx = (q << 8) + tid;
        int r = idx >> 3, ch = idx & 7;
        u32 off = (u32)(r * 144 + ch * 16);
        size_t src = (size_t)r * DHEAD + ch * 8;
        cp16s(smb + FQH + off, Qhg + src);
        cp16s(smb + FQL + off, Qlg + src);
    }
    stage_kv_tile(smb, 0, tid, Khg, Klg, Vhg, Vlg);
    CP_COMMIT();

    const int r0 = (wid << 4) + ln4;
    const float* prow0 = P + ((size_t)bh * NSEQ + n0 + r0) * PLD;
    const float* prow1 = prow0 + 8 * PLD;

    float o[8][4];
    #pragma unroll
    for (int n = 0; n < 8; n++)
        #pragma unroll
        for (int p = 0; p < 4; p++) o[n][p] = 0.0f;
    float lsum0 = 0.0f, lsum1 = 0.0f;

    for (int jt = 0; jt < 16; jt++) {
        const int j0 = jt << 7;

        CP_WAIT0();
        __syncthreads();                       // K/V tile ready

        #pragma unroll
        for (int half = 0; half < 2; half++) {
            // ---- S half = Q K^T : 16 rows x 64 cols, 3-term split -------------
            float c[8][4];
            #pragma unroll
            for (int n = 0; n < 8; n++)
                #pragma unroll
                for (int p = 0; p < 4; p++) c[n][p] = 0.0f;

            #pragma unroll
            for (int k = 0; k < 4; k++) {
                const int aoff = r0 * 72 + k * 16 + (lm4 << 1);
                u32 qh[4], ql[4];
                qh[0] = *(const u32*)(QhS + aoff);
                qh[1] = *(const u32*)(QhS + aoff + 8 * 72);
                qh[2] = *(const u32*)(QhS + aoff + 8);
                qh[3] = *(const u32*)(QhS + aoff + 8 * 72 + 8);
                ql[0] = *(const u32*)(QlS + aoff);
                ql[1] = *(const u32*)(QlS + aoff + 8 * 72);
                ql[2] = *(const u32*)(QlS + aoff + 8);
                ql[3] = *(const u32*)(QlS + aoff + 8 * 72 + 8);
                #pragma unroll
                for (int n = 0; n < 8; n++) {
                    const int boff = (half * 64 + n * 8 + ln4) * 72 + k * 16 + (lm4 << 1);
                    u32 bhh[2], bll[2];
                    bhh[0] = *(const u32*)(KhS + boff);
                    bhh[1] = *(const u32*)(KhS + boff + 8);
                    bll[0] = *(const u32*)(KlS + boff);
                    bll[1] = *(const u32*)(KlS + boff + 8);
                    mma_bf16(c[n], qh, bhh);
                    mma_bf16(c[n], ql, bhh);
                    mma_bf16(c[n], qh, bll);
                }
            }

            // ---- bias + exp (no max shift; scores bounded) ---------------------
            #pragma unroll
            for (int n = 0; n < 8; n++) {
                const int jb = j0 + half * 64 + n * 8 + (lm4 << 1);
                int t0 = (n0 + r0) - jb + 512;
                int ta = t0 < 0 ? 0 : (t0 > 1024 ? 1024 : t0);
                int t1 = t0 - 1;
                int tb = t1 < 0 ? 0 : (t1 > 1024 ? 1024 : t1);
                int t2 = t0 + 8;
                int tc = t2 < 0 ? 0 : (t2 > 1024 ? 1024 : t2);
                int t3 = t0 + 7;
                int td = t3 < 0 ? 0 : (t3 > 1024 ? 1024 : t3);
                float p0 = __expf(c[n][0] + prow0[ta]);
                float p1 = __expf(c[n][1] + prow0[tb]);
                float p2 = __expf(c[n][2] + prow1[tc]);
                float p3 = __expf(c[n][3] + prow1[td]);
                lsum0 += p0 + p1;
                lsum1 += p2 + p3;
                c[n][0] = p0; c[n][1] = p1; c[n][2] = p2; c[n][3] = p3;
            }

            // ---- pack P frags (C-frag -> A-frag reuse) -------------------------
            u32 Ah[4][4], Al[4][4];
            #pragma unroll
            for (int k = 0; k < 4; k++) {
                bfsplit2(c[2*k][0],   c[2*k][1],   Ah[k][0], Al[k][0]);
                bfsplit2(c[2*k][2],   c[2*k][3],   Ah[k][1], Al[k][1]);
                bfsplit2(c[2*k+1][0], c[2*k+1][1], Ah[k][2], Al[k][2]);
                bfsplit2(c[2*k+1][2], c[2*k+1][3], Ah[k][3], Al[k][3]);
            }

            // ---- O += P(half) V(half rows) -------------------------------------
            #pragma unroll
            for (int k = 0; k < 4; k++) {
                const int kk = half * 4 + k;
                #pragma unroll
                for (int n = 0; n < 8; n++) {
                    const int boff = (n * 8 + ln4) * 136 + kk * 16 + (lm4 << 1);
                    u32 vhh[2], vll[2];
                    vhh[0] = *(const u32*)(VhS + boff);
                    vhh[1] = *(const u32*)(VhS + boff + 8);
                    vll[0] = *(const u32*)(VlS + boff);
                    vll[1] = *(const u32*)(VlS + boff + 8);
                    mma_bf16(o[n], Ah[k], vhh);
                    mma_bf16(o[n], Al[k], vhh);
                    mma_bf16(o[n], Ah[k], vll);
                }
            }
        }

        __syncthreads();                       // all warps done reading K/V
        if (jt + 1 < 16) {
            stage_kv_tile(smb, j0 + 128, tid, Khg, Klg, Vhg, Vlg);
            CP_COMMIT();
        }
    }

    lsum0 += __shfl_xor_sync(0xffffffffu, lsum0, 1);
    lsum0 += __shfl_xor_sync(0xffffffffu, lsum0, 2);
    lsum1 += __shfl_xor_sync(0xffffffffu, lsum1, 1);
    lsum1 += __shfl_xor_sync(0xffffffffu, lsum1, 2);
    const float inv0 = 1.0f / lsum0;
    const float inv1 = 1.0f / lsum1;

    size_t ob0 = ((size_t)(b * NSEQ + n0 + r0)) * DIMM + (head << 6) + (lm4 << 1);
    size_t ob1 = ob0 + 8 * DIMM;
    #pragma unroll
    for (int n = 0; n < 8; n++) {
        u32 h, l;
        bfsplit2(o[n][0] * inv0, o[n][1] * inv0, h, l);
        *(u32*)(Ohi + ob0 + n * 8) = h;
        *(u32*)(Olo + ob0 + n * 8) = l;
        bfsplit2(o[n][2] * inv1, o[n][3] * inv1, h, l);
        *(u32*)(Ohi + ob1 + n * 8) = h;
        *(u32*)(Olo + ob1 + n * 8) = l;
    }
}

// ================= kernel 4: output projection (HMMA) ==============================
__global__ void __launch_bounds__(256, 2) out_hmma_kernel(
    const __nv_bfloat16* __restrict__ Ohi, const __nv_bfloat16* __restrict__ Olo,
    const __nv_bfloat16* __restrict__ WoThi, const __nv_bfloat16* __restrict__ WoTlo,
    const float* __restrict__ bo, float* __restrict__ out)
{
    extern __shared__ char smc[];
    const u32 smb = smem_u32(smc);
    const int m0 = blockIdx.x << 7;
    const int c0 = blockIdx.y << 7;

    float c[16][4];
    hmma_core(smb, smc, Ohi + (size_t)m0 * DIMM, Olo + (size_t)m0 * DIMM, DIMM,
              WoThi + (size_t)c0 * DIMM, WoTlo + (size_t)c0 * DIMM, DIMM, DIMM, c);

    const int tid = threadIdx.x, wid = tid >> 5, lane = tid & 31;
    const int ln4 = lane >> 2, lm4 = lane & 3;
    const size_t r0 = m0 + (wid << 4) + ln4;

    #pragma unroll
    for (int n = 0; n < 16; n++) {
        int col = c0 + n * 8 + (lm4 << 1);
        float2 bb = *(const float2*)(bo + col);
        *(float2*)(out + r0 * DIMM + col) = make_float2(c[n][0] + bb.x, c[n][1] + bb.y);
        *(float2*)(out + (r0 + 8) * DIMM + col) = make_float2(c[n][2] + bb.x, c[n][3] + bb.y);
    }
}

// ================= launch ==========================================================
extern "C" void kernel_launch(void* const* d_in, const int* in_sizes, int n_in,
                              void* d_out, int out_size)
{
    const float* x   = (const float*)d_in[0];
    const float* Wq  = (const float*)d_in[1];
    const float* Wkv = (const float*)d_in[2];
    const float* Wo  = (const float*)d_in[3];
    const float* bo  = (const float*)d_in[4];
    const float* rel = (const float*)d_in[5];
    float* out = (float*)d_out;

    __nv_bfloat16 *xh, *xl, *wth, *wtl, *woh, *wol, *rh, *rl;
    __nv_bfloat16 *qh, *ql, *kh, *kl, *vh, *vl, *oh, *ol;
    float *Pp;
    cudaGetSymbolAddress((void**)&xh,  g_xhi);
    cudaGetSymbolAddress((void**)&xl,  g_xlo);
    cudaGetSymbolAddress((void**)&wth, g_Wthi);
    cudaGetSymbolAddress((void**)&wtl, g_Wtlo);
    cudaGetSymbolAddress((void**)&woh, g_WoThi);
    cudaGetSymbolAddress((void**)&wol, g_WoTlo);
    cudaGetSymbolAddress((void**)&rh,  g_relhi);
    cudaGetSymbolAddress((void**)&rl,  g_rello);
    cudaGetSymbolAddress((void**)&qh,  g_Qhi);
    cudaGetSymbolAddress((void**)&ql,  g_Qlo);
    cudaGetSymbolAddress((void**)&kh,  g_Khi);
    cudaGetSymbolAddress((void**)&kl,  g_Klo);
    cudaGetSymbolAddress((void**)&vh,  g_Vhi);
    cudaGetSymbolAddress((void**)&vl,  g_Vlo);
    cudaGetSymbolAddress((void**)&oh,  g_Ohi);
    cudaGetSymbolAddress((void**)&ol,  g_Olo);
    cudaGetSymbolAddress((void**)&Pp,  g_P);

    cudaFuncSetAttribute(qkv_hmma_kernel,
                         cudaFuncAttributeMaxDynamicSharedMemorySize, GSM_SGL);
    cudaFuncSetAttribute(p_hmma_kernel,
                         cudaFuncAttributeMaxDynamicSharedMemorySize, GSM_SGL);
    cudaFuncSetAttribute(out_hmma_kernel,
                         cudaFuncAttributeMaxDynamicSharedMemorySize, GSM_SGL);
    cudaFuncSetAttribute(flash_kernel,
                         cudaFuncAttributeMaxDynamicSharedMemorySize, FSM_TOTAL);

    split_x_kernel<<<MROWS * DIMM / 512, 256>>>(x, xh, xl);
    split_w_kernel<<<2048, 256>>>(Wq, Wkv, Wo, wth, wtl, woh, wol);
    split_rel_kernel<<<144, 256>>>(rel, rh, rl);

    qkv_hmma_kernel<<<dim3(32, 12), 256, GSM_SGL>>>(xh, xl, wth, wtl,
                                                    qh, ql, kh, kl, vh, vl);
    p_hmma_kernel<<<dim3(256, 9), 256, GSM_SGL>>>(qh, ql, rh, rl, Pp);
    flash_kernel<<<dim3(16, 16), 256, FSM_TOTAL>>>(qh, ql, kh, kl, vh, vl, Pp, oh, ol);
    out_hmma_kernel<<<dim3(32, 4), 256, GSM_SGL>>>(oh, ol, woh, wol, bo, out);
}

// round 15
// speedup vs baseline: 2.1746x; 1.0215x over previous
#include <cuda_runtime.h>
#include <cuda_bf16.h>
#include <math.h>

#define BATCH   2
#define NSEQ    2048
#define HEADS   8
#define DHEAD   64
#define DIMM    512
#define BHDIM   16
#define MROWS   4096
#define QROWS   32768
#define TVALS   1025
#define PLD     1028
#define SCALE_F 0.125f

typedef unsigned long long u64;
typedef unsigned int u32;

// ---------------- device scratch ---------------------------------------------
__device__ __nv_bfloat16 g_xhi[MROWS * DIMM];         // [m][k]
__device__ __nv_bfloat16 g_xlo[MROWS * DIMM];
__device__ __nv_bfloat16 g_Wthi[1536 * DIMM];         // [c][k]
__device__ __nv_bfloat16 g_Wtlo[1536 * DIMM];
__device__ __nv_bfloat16 g_WoThi[DIMM * DIMM];        // [c][k]
__device__ __nv_bfloat16 g_WoTlo[DIMM * DIMM];
__device__ __nv_bfloat16 g_relhi[1152 * DHEAD];       // [t][d] zero-padded
__device__ __nv_bfloat16 g_rello[1152 * DHEAD];
__device__ __nv_bfloat16 g_Qhi[QROWS * DHEAD];        // [bh][n][d] scaled
__device__ __nv_bfloat16 g_Qlo[QROWS * DHEAD];
__device__ __nv_bfloat16 g_Khi[QROWS * DHEAD];        // [bh][n][d]
__device__ __nv_bfloat16 g_Klo[QROWS * DHEAD];
__device__ __nv_bfloat16 g_Vhi[QROWS * DHEAD];        // [bh][d][n]
__device__ __nv_bfloat16 g_Vlo[QROWS * DHEAD];
__device__ __nv_bfloat16 g_Ohi[MROWS * DIMM];         // [m][h*d]
__device__ __nv_bfloat16 g_Olo[MROWS * DIMM];
__device__ float g_P [(size_t)QROWS * PLD];

// ---------------- bf16 split helpers -------------------------------------------
__device__ __forceinline__ void bfsplit2(float f0, float f1, u32& hi, u32& lo) {
    __nv_bfloat16 h0 = __float2bfloat16(f0), h1 = __float2bfloat16(f1);
    __nv_bfloat16 g0 = __float2bfloat16(f0 - __bfloat162float(h0));
    __nv_bfloat16 g1 = __float2bfloat16(f1 - __bfloat162float(h1));
    hi = (u32)__bfloat16_as_ushort(h0) | ((u32)__bfloat16_as_ushort(h1) << 16);
    lo = (u32)__bfloat16_as_ushort(g0) | ((u32)__bfloat16_as_ushort(g1) << 16);
}
__device__ __forceinline__ void bfsplit1(float f, __nv_bfloat16& h, __nv_bfloat16& l) {
    h = __float2bfloat16(f);
    l = __float2bfloat16(f - __bfloat162float(h));
}

// ---------------- cp.async -------------------------------------------------------
__device__ __forceinline__ void cp16s(u32 dst, const void* src) {
    asm volatile("cp.async.ca.shared.global [%0], [%1], 16;" :: "r"(dst), "l"(src));
}
#define CP_COMMIT() asm volatile("cp.async.commit_group;")
#define CP_WAIT0()  asm volatile("cp.async.wait_group 0;")

__device__ __forceinline__ u32 smem_u32(const void* p) {
    u32 a;
    asm("{ .reg .u64 t; cvta.to.shared.u64 t, %1; cvt.u32.u64 %0, t; }" : "=r"(a) : "l"(p));
    return a;
}

// ---------------- HMMA m16n8k16 bf16 + ldmatrix -----------------------------------
__device__ __forceinline__ void mma_bf16(float* d, const u32* a, const u32* b) {
    asm volatile(
        "mma.sync.aligned.m16n8k16.row.col.f32.bf16.bf16.f32 "
        "{%0,%1,%2,%3}, {%4,%5,%6,%7}, {%8,%9}, {%0,%1,%2,%3};"
        : "+f"(d[0]), "+f"(d[1]), "+f"(d[2]), "+f"(d[3])
        : "r"(a[0]), "r"(a[1]), "r"(a[2]), "r"(a[3]), "r"(b[0]), "r"(b[1]));
}
__device__ __forceinline__ void ldsm4(u32* r, u32 addr) {
    asm volatile("ldmatrix.sync.aligned.m8n8.x4.shared.b16 {%0,%1,%2,%3}, [%4];"
        : "=r"(r[0]), "=r"(r[1]), "=r"(r[2]), "=r"(r[3]) : "r"(addr));
}
// A-type x4 address (16x16 tile, row stride S bytes):
//   lane 0-7: rows 0-7/col0  8-15: rows 8-15/col0  16-23: rows 0-7/col+16B  24-31: rows 8-15/col+16B
__device__ __forceinline__ u32 ldsmA_addr(u32 base, int lane, int rowbase, int strideB) {
    int row = rowbase + (lane & 7) + (((lane >> 3) & 1) << 3);
    return base + (u32)(row * strideB) + (u32)((lane >> 4) << 4);
}
// B-type x4 address (2 n-octets x 2 k-octets):
//   lane 0-7: rows r/col0   8-15: rows r/col+16B   16-23: rows r+8/col0   24-31: rows r+8/col+16B
//   regs: r0=b0(oct0) r1=b1(oct0) r2=b0(oct1) r3=b1(oct1)
__device__ __forceinline__ u32 ldsmB_addr(u32 base, int lane, int strideB) {
    int row = (lane & 7) + ((lane >> 4) << 3);
    return base + (u32)(row * strideB) + (u32)(((lane >> 3) & 1) << 4);
}

// ================= shared HMMA GEMM core (single-buffer, 2 CTAs/SM) ===============
#define GSM_SGL 73728

__device__ __forceinline__ void hmma_stage(
    u32 smb, int k0, int tid,
    const __nv_bfloat16* Ah, const __nv_bfloat16* Al, int lda,
    const __nv_bfloat16* Bh, const __nv_bfloat16* Bl, int ldb)
{
    #pragma unroll
    for (int q = 0; q < 4; q++) {
        int idx = (q << 8) + tid;
        int r = idx >> 3, ch = idx & 7;
        u32 off = (u32)(r * 144 + ch * 16);
        size_t sa = (size_t)r * lda + k0 + ch * 8;
        size_t sb = (size_t)r * ldb + k0 + ch * 8;
        cp16s(smb + off,         Ah + sa);
        cp16s(smb + 18432 + off, Al + sa);
        cp16s(smb + 36864 + off, Bh + sb);
        cp16s(smb + 55296 + off, Bl + sb);
    }
}

__device__ __forceinline__ void hmma_core(
    u32 smb,
    const __nv_bfloat16* Ah, const __nv_bfloat16* Al, int lda,
    const __nv_bfloat16* Bh, const __nv_bfloat16* Bl, int ldb,
    int kdim, float (&c)[16][4])
{
    const int tid = threadIdx.x;
    const int wid = tid >> 5, lane = tid & 31;

    const u32 aH = ldsmA_addr(smb,         lane, wid << 4, 144);
    const u32 aL = ldsmA_addr(smb + 18432, lane, wid << 4, 144);
    const u32 bH = ldsmB_addr(smb + 36864, lane, 144);
    const u32 bL = ldsmB_addr(smb + 55296, lane, 144);

    #pragma unroll
    for (int n = 0; n < 16; n++)
        #pragma unroll
        for (int p = 0; p < 4; p++) c[n][p] = 0.0f;

    hmma_stage(smb, 0, tid, Ah, Al, lda, Bh, Bl, ldb);
    CP_COMMIT();

    const int nchunks = kdim >> 6;
    for (int kc = 0; kc < nchunks; kc++) {
        CP_WAIT0();
        __syncthreads();

        #pragma unroll
        for (int k = 0; k < 4; k++) {
            u32 ah[4], al[4];
            ldsm4(ah, aH + (k << 5));
            ldsm4(al, aL + (k << 5));
            #pragma unroll
            for (int np = 0; np < 8; np++) {
                u32 bh4[4], bl4[4];
                ldsm4(bh4, bH + (u32)(np * 16 * 144) + (k << 5));
                ldsm4(bl4, bL + (u32)(np * 16 * 144) + (k << 5));
                mma_bf16(c[np*2],   ah, &bh4[0]);
                mma_bf16(c[np*2],   al, &bh4[0]);
                mma_bf16(c[np*2],   ah, &bl4[0]);
                mma_bf16(c[np*2+1], ah, &bh4[2]);
                mma_bf16(c[np*2+1], al, &bh4[2]);
                mma_bf16(c[np*2+1], ah, &bl4[2]);
            }
        }
        __syncthreads();
        if (kc + 1 < nchunks) {
            hmma_stage(smb, (kc + 1) << 6, tid, Ah, Al, lda, Bh, Bl, ldb);
            CP_COMMIT();
        }
    }
}

// ================= split prepasses =================================================
__global__ void __launch_bounds__(256) split_x_kernel(
    const float* __restrict__ x,
    __nv_bfloat16* __restrict__ xhi, __nv_bfloat16* __restrict__ xlo)
{
    int i = blockIdx.x * 256 + threadIdx.x;
    if (i < MROWS * DIMM / 2) {
        float2 f = *(const float2*)(x + 2 * (size_t)i);
        u32 h, l;
        bfsplit2(f.x, f.y, h, l);
        *(u32*)(xhi + 2 * (size_t)i) = h;
        *(u32*)(xlo + 2 * (size_t)i) = l;
    }
}

__global__ void __launch_bounds__(256) split_w_kernel(
    const float* __restrict__ Wq, const float* __restrict__ Wkv,
    const float* __restrict__ Wo,
    __nv_bfloat16* __restrict__ Wthi, __nv_bfloat16* __restrict__ Wtlo,
    __nv_bfloat16* __restrict__ WoThi, __nv_bfloat16* __restrict__ WoTlo)
{
    int idx = blockIdx.x * 256 + threadIdx.x;
    if (idx < 1536 * 256) {
        int c = idx >> 8, k = (idx & 255) << 1;
        float f0, f1;
        if (c < 512) { f0 = Wq[(size_t)k * 512 + c];  f1 = Wq[(size_t)(k+1) * 512 + c]; }
        else { f0 = Wkv[(size_t)k * 1024 + c - 512]; f1 = Wkv[(size_t)(k+1) * 1024 + c - 512]; }
        u32 h, l;
        bfsplit2(f0, f1, h, l);
        *(u32*)(Wthi + (size_t)c * 512 + k) = h;
        *(u32*)(Wtlo + (size_t)c * 512 + k) = l;
    } else if (idx < 1536 * 256 + 512 * 256) {
        int j = idx - 1536 * 256;
        int c = j >> 8, k = (j & 255) << 1;
        float f0 = Wo[(size_t)k * 512 + c], f1 = Wo[(size_t)(k+1) * 512 + c];
        u32 h, l;
        bfsplit2(f0, f1, h, l);
        *(u32*)(WoThi + (size_t)c * 512 + k) = h;
        *(u32*)(WoTlo + (size_t)c * 512 + k) = l;
    }
}

__global__ void __launch_bounds__(256) split_rel_kernel(
    const float* __restrict__ rel,
    __nv_bfloat16* __restrict__ relhi, __nv_bfloat16* __restrict__ rello)
{
    int idx = blockIdx.x * 256 + threadIdx.x;
    if (idx < 1152 * 32) {
        int t = idx >> 5, dp = (idx & 31) << 1;
        float f0 = 0.0f, f1 = 0.0f;
        if (t < TVALS) {
            f0 = rel[(size_t)t * DHEAD + dp];
            f1 = rel[(size_t)t * DHEAD + dp + 1];
        }
        u32 h, l;
        bfsplit2(f0, f1, h, l);
        *(u32*)(relhi + (size_t)t * DHEAD + dp) = h;
        *(u32*)(rello + (size_t)t * DHEAD + dp) = l;
    }
}

// ================= kernel 1: QKV projection (HMMA) =================================
__global__ void __launch_bounds__(256, 2) qkv_hmma_kernel(
    const __nv_bfloat16* __restrict__ xhi, const __nv_bfloat16* __restrict__ xlo,
    const __nv_bfloat16* __restrict__ Wthi, const __nv_bfloat16* __restrict__ Wtlo,
    __nv_bfloat16* __restrict__ Qhi, __nv_bfloat16* __restrict__ Qlo,
    __nv_bfloat16* __restrict__ Khi, __nv_bfloat16* __restrict__ Klo,
    __nv_bfloat16* __restrict__ Vhi, __nv_bfloat16* __restrict__ Vlo)
{
    extern __shared__ char smc[];
    const u32 smb = smem_u32(smc);
    const int m0 = blockIdx.x << 7;
    const int c0 = blockIdx.y << 7;

    float c[16][4];
    hmma_core(smb, xhi + (size_t)m0 * DIMM, xlo + (size_t)m0 * DIMM, DIMM,
              Wthi + (size_t)c0 * DIMM, Wtlo + (size_t)c0 * DIMM, DIMM, DIMM, c);

    const int tid = threadIdx.x, wid = tid >> 5, lane = tid & 31;
    const int ln4 = lane >> 2, lm4 = lane & 3;
    const int b = m0 >> 11;
    const int ns0 = (m0 & 2047) + (wid << 4) + ln4;

    if (c0 < 1024) {
        const float sc = (c0 < 512) ? SCALE_F : 1.0f;
        __nv_bfloat16* Dh = (c0 < 512) ? Qhi : Khi;
        __nv_bfloat16* Dl = (c0 < 512) ? Qlo : Klo;
        #pragma unroll
        for (int n = 0; n < 16; n++) {
            int col = (c0 & 511) + n * 8 + (lm4 << 1);
            int head = col >> 6, dl = col & 63;
            size_t base0 = (((size_t)(b * HEADS + head)) * NSEQ + ns0) * DHEAD + dl;
            size_t base1 = base0 + 8 * DHEAD;
            u32 h, l;
            bfsplit2(c[n][0] * sc, c[n][1] * sc, h, l);
            *(u32*)(Dh + base0) = h; *(u32*)(Dl + base0) = l;
            bfsplit2(c[n][2] * sc, c[n][3] * sc, h, l);
            *(u32*)(Dh + base1) = h; *(u32*)(Dl + base1) = l;
        }
    } else {
        #pragma unroll
        for (int n = 0; n < 16; n++) {
            int col = (c0 - 1024) + n * 8 + (lm4 << 1);
            int head = col >> 6, d0 = col & 63;
            size_t rowbase = ((size_t)(b * HEADS + head) * DHEAD + d0) * NSEQ;
            #pragma unroll
            for (int e = 0; e < 2; e++) {
                __nv_bfloat16 h, l;
                bfsplit1(c[n][e], h, l);
                Vhi[rowbase + (size_t)e * NSEQ + ns0] = h;
                Vlo[rowbase + (size_t)e * NSEQ + ns0] = l;
                bfsplit1(c[n][2 + e], h, l);
                Vhi[rowbase + (size_t)e * NSEQ + ns0 + 8] = h;
                Vlo[rowbase + (size_t)e * NSEQ + ns0 + 8] = l;
            }
        }
    }
}

// ================= kernel 2: P = Qscaled @ rel^T (HMMA, K=64) =======================
__global__ void __launch_bounds__(256, 2) p_hmma_kernel(
    const __nv_bfloat16* __restrict__ Qhi, const __nv_bfloat16* __restrict__ Qlo,
    const __nv_bfloat16* __restrict__ relhi, const __nv_bfloat16* __restrict__ rello,
    float* __restrict__ P)
{
    extern __shared__ char smc[];
    const u32 smb = smem_u32(smc);
    const int m0 = blockIdx.x << 7;
    const int t0 = blockIdx.y << 7;

    float c[16][4];
    hmma_core(smb, Qhi + (size_t)m0 * DHEAD, Qlo + (size_t)m0 * DHEAD, DHEAD,
              relhi + (size_t)t0 * DHEAD, rello + (size_t)t0 * DHEAD, DHEAD, DHEAD, c);

    const int tid = threadIdx.x, wid = tid >> 5, lane = tid & 31;
    const int ln4 = lane >> 2, lm4 = lane & 3;
    const size_t r0 = m0 + (wid << 4) + ln4;

    #pragma unroll
    for (int n = 0; n < 16; n++) {
        int col = t0 + n * 8 + (lm4 << 1);
        if (col + 1 < TVALS) {
            *(float2*)(P + r0 * PLD + col) = make_float2(c[n][0], c[n][1]);
            *(float2*)(P + (r0 + 8) * PLD + col) = make_float2(c[n][2], c[n][3]);
        } else if (col < TVALS) {
            P[r0 * PLD + col] = c[n][0];
            P[(r0 + 8) * PLD + col] = c[n][2];
        }
    }
}

// ================= kernel 3: HMMA flash attention (2 CTAs/SM, ldmatrix) =============
#define FQH 0
#define FQL 18432
#define FKH 36864
#define FKL 55296
#define FVH 73728
#define FVL 91136
#define FSM_TOTAL 108544

__device__ __forceinline__ void stage_kv_tile(
    u32 smb, int j0, int tid,
    const __nv_bfloat16* Kh, const __nv_bfloat16* Kl,
    const __nv_bfloat16* Vh, const __nv_bfloat16* Vl)
{
    #pragma unroll
    for (int q = 0; q < 4; q++) {
        int idx = (q << 8) + tid;
        int r = idx >> 3, ch = idx & 7;
        u32 off = (u32)(r * 144 + ch * 16);
        size_t src = (size_t)(j0 + r) * DHEAD + ch * 8;
        cp16s(smb + FKH + off, Kh + src);
        cp16s(smb + FKL + off, Kl + src);
    }
    #pragma unroll
    for (int q = 0; q < 4; q++) {
        int idx = (q << 8) + tid;
        int d = idx >> 4, ch = idx & 15;
        u32 off = (u32)(d * 272 + ch * 16);
        size_t src = (size_t)d * NSEQ + j0 + ch * 8;
        cp16s(smb + FVH + off, Vh + src);
        cp16s(smb + FVL + off, Vl + src);
    }
}

__global__ void __launch_bounds__(256, 2) flash_kernel(
    const __nv_bfloat16* __restrict__ Qhi, const __nv_bfloat16* __restrict__ Qlo,
    const __nv_bfloat16* __restrict__ Khi, const __nv_bfloat16* __restrict__ Klo,
    const __nv_bfloat16* __restrict__ Vhi, const __nv_bfloat16* __restrict__ Vlo,
    const float* __restrict__ P,
    __nv_bfloat16* __restrict__ Ohi, __nv_bfloat16* __restrict__ Olo)
{
    extern __shared__ char smc[];
    const u32 smb = smem_u32(smc);

    const int tid  = threadIdx.x;
    const int wid  = tid >> 5, lane = tid & 31;
    const int ln4  = lane >> 2;
    const int lm4  = lane & 3;
    const int bh   = blockIdx.y, n0 = blockIdx.x << 7;
    const int b    = bh >> 3, head = bh & 7;

    const __nv_bfloat16* Qhg = Qhi + ((size_t)bh * NSEQ + n0) * DHEAD;
    const __nv_bfloat16* Qlg = Qlo + ((size_t)bh * NSEQ + n0) * DHEAD;
    const __nv_bfloat16* Khg = Khi + (size_t)bh * NSEQ * DHEAD;
    const __nv_bfloat16* Klg = Klo + (size_t)bh * NSEQ * DHEAD;
    const __nv_bfloat16* Vhg = Vhi + (size_t)bh * DHEAD * NSEQ;
    const __nv_bfloat16* Vlg = Vlo + (size_t)bh * DHEAD * NSEQ;

    // ldmatrix addresses
    const u32 qH = ldsmA_addr(smb + FQH, lane, wid << 4, 144);
    const u32 qL = ldsmA_addr(smb + FQL, lane, wid << 4, 144);
    const u32 kH = ldsmB_addr(smb + FKH, lane, 144);
    const u32 kL = ldsmB_addr(smb + FKL, lane, 144);
    const u32 vH = ldsmB_addr(smb + FVH, lane, 272);
    const u32 vL = ldsmB_addr(smb + FVL, lane, 272);

    // stage Q (once) and K/V tile 0
    #pragma unroll
    for (int q = 0; q < 4; q++) {
        int idx = (q << 8) + tid;
        int r = idx >> 3, ch = idx & 7;
        u32 off = (u32)(r * 144 + ch * 16);
        size_t src = (size_t)r * DHEAD + ch * 8;
        cp16s(smb + FQH + off, Qhg + src);
        cp16s(smb + FQL + off, Qlg + src);
    }
    stage_kv_tile(smb, 0, tid, Khg, Klg, Vhg, Vlg);
    CP_COMMIT();

    const int r0 = (wid << 4) + ln4;
    const float* prow0 = P + ((size_t)bh * NSEQ + n0 + r0) * PLD;
    const float* prow1 = prow0 + 8 * PLD;

    float o[8][4];
    #pragma unroll
    for (int n = 0; n < 8; n++)
        #pragma unroll
        for (int p = 0; p < 4; p++) o[n][p] = 0.0f;
    float lsum0 = 0.0f, lsum1 = 0.0f;

    for (int jt = 0; jt < 16; jt++) {
        const int j0 = jt << 7;

        CP_WAIT0();
        __syncthreads();                       // K/V tile ready

        #pragma unroll
        for (int half = 0; half < 2; half++) {
            // ---- S half = Q K^T : 16 rows x 64 cols, 3-term split -------------
            float c[8][4];
            #pragma unroll
            for (int n = 0; n < 8; n++)
                #pragma unroll
                for (int p = 0; p < 4; p++) c[n][p] = 0.0f;

            #pragma unroll
            for (int k = 0; k < 4; k++) {
                u32 qh4[4], ql4[4];
                ldsm4(qh4, qH + (k << 5));
                ldsm4(ql4, qL + (k << 5));
                #pragma unroll
                for (int np = 0; np < 4; np++) {
                    u32 rowoff = (u32)((half * 64 + np * 16) * 144);
                    u32 bh4[4], bl4[4];
                    ldsm4(bh4, kH + rowoff + (k << 5));
                    ldsm4(bl4, kL + rowoff + (k << 5));
                    mma_bf16(c[np*2],   qh4, &bh4[0]);
                    mma_bf16(c[np*2],   ql4, &bh4[0]);
                    mma_bf16(c[np*2],   qh4, &bl4[0]);
                    mma_bf16(c[np*2+1], qh4, &bh4[2]);
                    mma_bf16(c[np*2+1], ql4, &bh4[2]);
                    mma_bf16(c[np*2+1], qh4, &bl4[2]);
                }
            }

            // ---- bias + exp (no max shift; scores bounded) ---------------------
            #pragma unroll
            for (int n = 0; n < 8; n++) {
                const int jb = j0 + half * 64 + n * 8 + (lm4 << 1);
                int t0 = (n0 + r0) - jb + 512;
                int ta = t0 < 0 ? 0 : (t0 > 1024 ? 1024 : t0);
                int t1 = t0 - 1;
                int tb = t1 < 0 ? 0 : (t1 > 1024 ? 1024 : t1);
                int t2 = t0 + 8;
                int tc = t2 < 0 ? 0 : (t2 > 1024 ? 1024 : t2);
                int t3 = t0 + 7;
                int td = t3 < 0 ? 0 : (t3 > 1024 ? 1024 : t3);
                float p0 = __expf(c[n][0] + prow0[ta]);
                float p1 = __expf(c[n][1] + prow0[tb]);
                float p2 = __expf(c[n][2] + prow1[tc]);
                float p3 = __expf(c[n][3] + prow1[td]);
                lsum0 += p0 + p1;
                lsum1 += p2 + p3;
                c[n][0] = p0; c[n][1] = p1; c[n][2] = p2; c[n][3] = p3;
            }

            // ---- pack P frags (C-frag -> A-frag reuse) -------------------------
            u32 Ah[4][4], Al[4][4];
            #pragma unroll
            for (int k = 0; k < 4; k++) {
                bfsplit2(c[2*k][0],   c[2*k][1],   Ah[k][0], Al[k][0]);
                bfsplit2(c[2*k][2],   c[2*k][3],   Ah[k][1], Al[k][1]);
                bfsplit2(c[2*k+1][0], c[2*k+1][1], Ah[k][2], Al[k][2]);
                bfsplit2(c[2*k+1][2], c[2*k+1][3], Ah[k][3], Al[k][3]);
            }

            // ---- O += P(half) V(half k rows) -----------------------------------
            #pragma unroll
            for (int k = 0; k < 4; k++) {
                const int kk = half * 4 + k;
                #pragma unroll
                for (int np = 0; np < 4; np++) {
                    u32 rowoff = (u32)(np * 16 * 272);
                    u32 vh4[4], vl4[4];
                    ldsm4(vh4, vH + rowoff + (kk << 5));
                    ldsm4(vl4, vL + rowoff + (kk << 5));
                    mma_bf16(o[np*2],   Ah[k], &vh4[0]);
                    mma_bf16(o[np*2],   Al[k], &vh4[0]);
                    mma_bf16(o[np*2],   Ah[k], &vl4[0]);
                    mma_bf16(o[np*2+1], Ah[k], &vh4[2]);
                    mma_bf16(o[np*2+1], Al[k], &vh4[2]);
                    mma_bf16(o[np*2+1], Ah[k], &vl4[2]);
                }
            }
        }

        __syncthreads();                       // all warps done reading K/V
        if (jt + 1 < 16) {
            stage_kv_tile(smb, j0 + 128, tid, Khg, Klg, Vhg, Vlg);
            CP_COMMIT();
        }
    }

    lsum0 += __shfl_xor_sync(0xffffffffu, lsum0, 1);
    lsum0 += __shfl_xor_sync(0xffffffffu, lsum0, 2);
    lsum1 += __shfl_xor_sync(0xffffffffu, lsum1, 1);
    lsum1 += __shfl_xor_sync(0xffffffffu, lsum1, 2);
    const float inv0 = 1.0f / lsum0;
    const float inv1 = 1.0f / lsum1;

    size_t ob0 = ((size_t)(b * NSEQ + n0 + r0)) * DIMM + (head << 6) + (lm4 << 1);
    size_t ob1 = ob0 + 8 * DIMM;
    #pragma unroll
    for (int n = 0; n < 8; n++) {
        u32 h, l;
        bfsplit2(o[n][0] * inv0, o[n][1] * inv0, h, l);
        *(u32*)(Ohi + ob0 + n * 8) = h;
        *(u32*)(Olo + ob0 + n * 8) = l;
        bfsplit2(o[n][2] * inv1, o[n][3] * inv1, h, l);
        *(u32*)(Ohi + ob1 + n * 8) = h;
        *(u32*)(Olo + ob1 + n * 8) = l;
    }
}

// ================= kernel 4: output projection (HMMA) ==============================
__global__ void __launch_bounds__(256, 2) out_hmma_kernel(
    const __nv_bfloat16* __restrict__ Ohi, const __nv_bfloat16* __restrict__ Olo,
    const __nv_bfloat16* __restrict__ WoThi, const __nv_bfloat16* __restrict__ WoTlo,
    const float* __restrict__ bo, float* __restrict__ out)
{
    extern __shared__ char smc[];
    const u32 smb = smem_u32(smc);
    const int m0 = blockIdx.x << 7;
    const int c0 = blockIdx.y << 7;

    float c[16][4];
    hmma_core(smb, Ohi + (size_t)m0 * DIMM, Olo + (size_t)m0 * DIMM, DIMM,
              WoThi + (size_t)c0 * DIMM, WoTlo + (size_t)c0 * DIMM, DIMM, DIMM, c);

    const int tid = threadIdx.x, wid = tid >> 5, lane = tid & 31;
    const int ln4 = lane >> 2, lm4 = lane & 3;
    const size_t r0 = m0 + (wid << 4) + ln4;

    #pragma unroll
    for (int n = 0; n < 16; n++) {
        int col = c0 + n * 8 + (lm4 << 1);
        float2 bb = *(const float2*)(bo + col);
        *(float2*)(out + r0 * DIMM + col) = make_float2(c[n][0] + bb.x, c[n][1] + bb.y);
        *(float2*)(out + (r0 + 8) * DIMM + col) = make_float2(c[n][2] + bb.x, c[n][3] + bb.y);
    }
}

// ================= launch ==========================================================
extern "C" void kernel_launch(void* const* d_in, const int* in_sizes, int n_in,
                              void* d_out, int out_size)
{
    const float* x   = (const float*)d_in[0];
    const float* Wq  = (const float*)d_in[1];
    const float* Wkv = (const float*)d_in[2];
    const float* Wo  = (const float*)d_in[3];
    const float* bo  = (const float*)d_in[4];
    const float* rel = (const float*)d_in[5];
    float* out = (float*)d_out;

    __nv_bfloat16 *xh, *xl, *wth, *wtl, *woh, *wol, *rh, *rl;
    __nv_bfloat16 *qh, *ql, *kh, *kl, *vh, *vl, *oh, *ol;
    float *Pp;
    cudaGetSymbolAddress((void**)&xh,  g_xhi);
    cudaGetSymbolAddress((void**)&xl,  g_xlo);
    cudaGetSymbolAddress((void**)&wth, g_Wthi);
    cudaGetSymbolAddress((void**)&wtl, g_Wtlo);
    cudaGetSymbolAddress((void**)&woh, g_WoThi);
    cudaGetSymbolAddress((void**)&wol, g_WoTlo);
    cudaGetSymbolAddress((void**)&rh,  g_relhi);
    cudaGetSymbolAddress((void**)&rl,  g_rello);
    cudaGetSymbolAddress((void**)&qh,  g_Qhi);
    cudaGetSymbolAddress((void**)&ql,  g_Qlo);
    cudaGetSymbolAddress((void**)&kh,  g_Khi);
    cudaGetSymbolAddress((void**)&kl,  g_Klo);
    cudaGetSymbolAddress((void**)&vh,  g_Vhi);
    cudaGetSymbolAddress((void**)&vl,  g_Vlo);
    cudaGetSymbolAddress((void**)&oh,  g_Ohi);
    cudaGetSymbolAddress((void**)&ol,  g_Olo);
    cudaGetSymbolAddress((void**)&Pp,  g_P);

    cudaFuncSetAttribute(qkv_hmma_kernel,
                         cudaFuncAttributeMaxDynamicSharedMemorySize, GSM_SGL);
    cudaFuncSetAttribute(p_hmma_kernel,
                         cudaFuncAttributeMaxDynamicSharedMemorySize, GSM_SGL);
    cudaFuncSetAttribute(out_hmma_kernel,
                         cudaFuncAttributeMaxDynamicSharedMemorySize, GSM_SGL);
    cudaFuncSetAttribute(flash_kernel,
                         cudaFuncAttributeMaxDynamicSharedMemorySize, FSM_TOTAL);

    split_x_kernel<<<MROWS * DIMM / 512, 256>>>(x, xh, xl);
    split_w_kernel<<<2048, 256>>>(Wq, Wkv, Wo, wth, wtl, woh, wol);
    split_rel_kernel<<<144, 256>>>(rel, rh, rl);

    qkv_hmma_kernel<<<dim3(32, 12), 256, GSM_SGL>>>(xh, xl, wth, wtl,
                                                    qh, ql, kh, kl, vh, vl);
    p_hmma_kernel<<<dim3(256, 9), 256, GSM_SGL>>>(qh, ql, rh, rl, Pp);
    flash_kernel<<<dim3(16, 16), 256, FSM_TOTAL>>>(qh, ql, kh, kl, vh, vl, Pp, oh, ol);
    out_hmma_kernel<<<dim3(32, 4), 256, GSM_SGL>>>(oh, ol, woh, wol, bo, out);
}